// round 2
// baseline (speedup 1.0000x reference)
#include <cuda_runtime.h>
#include <cstdint>
#include <cstddef>

#define TSTEPS 512
#define NB     128        // batch
#define DIN    1024       // input size
#define DH     1024       // hidden
#define NR     256        // rank
#define N4     4096       // 4*DH
#define NSPAR  768        // DH-NR

// ---- device scratch (no dynamic allocation allowed) ----
__device__ float g_Wx[(size_t)N4 * DIN];                 // 16 MB  combined x weights [n][k]
__device__ float g_Wh[(size_t)N4 * DH];                  // 16 MB  combined h weights [n][k]
__device__ float g_bias[N4];
__device__ float g_preX[(size_t)TSTEPS * NB * N4];       // 1 GiB  x-side preactivations (+bias)
__device__ float g_h[2][NB * DH];                        // h ping-pong
__device__ float g_c[NB * DH];                           // cell state

// ---------------- helpers ----------------
__device__ __forceinline__ uint32_t f2tf32(float f) {
    uint32_t u;
    asm("cvt.rna.tf32.f32 %0, %1;" : "=r"(u) : "f"(f));
    return u;
}

__device__ __forceinline__ void mma_tf32(float* c, const uint32_t* a, const uint32_t* b) {
    asm volatile(
        "mma.sync.aligned.m16n8k8.row.col.f32.tf32.tf32.f32 "
        "{%0,%1,%2,%3}, {%4,%5,%6,%7}, {%8,%9}, {%0,%1,%2,%3};"
        : "+f"(c[0]), "+f"(c[1]), "+f"(c[2]), "+f"(c[3])
        : "r"(a[0]), "r"(a[1]), "r"(a[2]), "r"(a[3]), "r"(b[0]), "r"(b[1]));
}

__device__ __forceinline__ float fsigmoid(float x) {
    return 1.0f / (1.0f + __expf(-x));
}

// ---------------- init state ----------------
__global__ void k_init(const float* __restrict__ h0, const float* __restrict__ c0) {
    int i = blockIdx.x * blockDim.x + threadIdx.x;
    if (i < NB * DH) { g_h[0][i] = h0[i]; g_c[i] = c0[i]; }
}

// ---------------- rich rows (copy A) + bias ----------------
__global__ void k_rich_bias(const float* __restrict__ Ax, const float* __restrict__ Ah,
                            const float* __restrict__ bx, const float* __restrict__ bh) {
    int i = blockIdx.x * blockDim.x + threadIdx.x;     // over 4*NR*DIN
    if (i < 4 * NR * DIN) {
        int k   = i % DIN;
        int row = i / DIN;          // g*NR + j
        int g = row / NR, j = row % NR;
        size_t w = ((size_t)(g * DH + j)) * DIN + k;
        g_Wx[w] = Ax[i];
        g_Wh[w] = Ah[i];
    }
    if (i < N4) g_bias[i] = bx[i] + bh[i];
}

// ---------------- sparse rows: W[g*DH+NR+m][k] = sum_r B[g][m][r]*C[g][r][k] ----------------
// grid: (DIN/128, NSPAR/8, 8)  z<4 -> x-branch gate z ; z>=4 -> h-branch gate z-4
__global__ void k_spar(const float* __restrict__ Bx, const float* __restrict__ Cx,
                       const float* __restrict__ Bh, const float* __restrict__ Ch) {
    int z = blockIdx.z;
    int g = z & 3;
    const float* Bp = (z < 4) ? Bx : Bh;
    const float* Cp = (z < 4) ? Cx : Ch;
    float*       Wp = (z < 4) ? g_Wx : g_Wh;
    int m0  = blockIdx.y * 8;
    int col = blockIdx.x * 128 + threadIdx.x;

    __shared__ float Bs[8][NR];
    for (int i = threadIdx.x; i < 8 * NR; i += 128) {
        int mm = i / NR, rr = i % NR;
        Bs[mm][rr] = Bp[(size_t)(g * NSPAR + m0 + mm) * NR + rr];
    }
    __syncthreads();

    float acc[8];
#pragma unroll
    for (int mm = 0; mm < 8; mm++) acc[mm] = 0.0f;
    for (int r = 0; r < NR; ++r) {
        float cv = Cp[(size_t)(g * NR + r) * DIN + col];
#pragma unroll
        for (int mm = 0; mm < 8; mm++) acc[mm] += Bs[mm][r] * cv;
    }
#pragma unroll
    for (int mm = 0; mm < 8; mm++)
        Wp[(size_t)(g * DH + NR + m0 + mm) * DIN + col] = acc[mm];
}

// ---------------- X GEMM: preX[M=65536, N=4096] = x @ Wx^T + bias  (tf32 mma) ----------------
// BM=128, BN=128, BK=32, 256 threads (8 warps: 2x4), warp tile 64x32
__global__ __launch_bounds__(256) void k_xgemm(const float* __restrict__ x) {
    __shared__ float As[128][36];
    __shared__ float Bs[128][36];
    const int tid  = threadIdx.x;
    const int lane = tid & 31;
    const int warp = tid >> 5;
    const int wm   = warp & 1;       // m offset 64
    const int wn   = warp >> 1;      // n offset 32
    const size_t mBase = (size_t)blockIdx.y * 128;
    const int    nBase = blockIdx.x * 128;
    const int lr = tid >> 3;         // 0..31
    const int lc = (tid & 7) * 4;    // 0,4,...,28

    float acc[4][4][4];
#pragma unroll
    for (int a = 0; a < 4; a++)
#pragma unroll
        for (int b = 0; b < 4; b++)
#pragma unroll
            for (int d = 0; d < 4; d++) acc[a][b][d] = 0.0f;

    float4 ra[4], rb[4];
#pragma unroll
    for (int p = 0; p < 4; p++) {
        int r = lr + p * 32;
        ra[p] = *(const float4*)&x[(mBase + r) * DIN + lc];
        rb[p] = *(const float4*)&g_Wx[((size_t)(nBase + r)) * DIN + lc];
    }

    for (int k0 = 0; k0 < DIN; k0 += 32) {
#pragma unroll
        for (int p = 0; p < 4; p++) {
            int r = lr + p * 32;
            *(float4*)&As[r][lc] = ra[p];
            *(float4*)&Bs[r][lc] = rb[p];
        }
        __syncthreads();
        int kn = k0 + 32;
        if (kn < DIN) {
#pragma unroll
            for (int p = 0; p < 4; p++) {
                int r = lr + p * 32;
                ra[p] = *(const float4*)&x[(mBase + r) * DIN + kn + lc];
                rb[p] = *(const float4*)&g_Wx[((size_t)(nBase + r)) * DIN + kn + lc];
            }
        }
#pragma unroll
        for (int kk = 0; kk < 32; kk += 8) {
            uint32_t af[4][4];
            uint32_t bf[4][2];
#pragma unroll
            for (int mf = 0; mf < 4; mf++) {
                int rb0 = wm * 64 + mf * 16 + (lane >> 2);
                af[mf][0] = f2tf32(As[rb0][kk + (lane & 3)]);
                af[mf][1] = f2tf32(As[rb0 + 8][kk + (lane & 3)]);
                af[mf][2] = f2tf32(As[rb0][kk + 4 + (lane & 3)]);
                af[mf][3] = f2tf32(As[rb0 + 8][kk + 4 + (lane & 3)]);
            }
#pragma unroll
            for (int nf = 0; nf < 4; nf++) {
                int nb0 = wn * 32 + nf * 8 + (lane >> 2);
                bf[nf][0] = f2tf32(Bs[nb0][kk + (lane & 3)]);
                bf[nf][1] = f2tf32(Bs[nb0][kk + 4 + (lane & 3)]);
            }
#pragma unroll
            for (int mf = 0; mf < 4; mf++)
#pragma unroll
                for (int nf = 0; nf < 4; nf++)
                    mma_tf32(acc[mf][nf], af[mf], bf[nf]);
        }
        __syncthreads();
    }

#pragma unroll
    for (int mf = 0; mf < 4; mf++) {
#pragma unroll
        for (int nf = 0; nf < 4; nf++) {
            int r0 = wm * 64 + mf * 16 + (lane >> 2);
            int c0 = wn * 32 + nf * 8 + (lane & 3) * 2;
            int n  = nBase + c0;
            size_t base = (mBase + r0) * (size_t)N4 + n;
            g_preX[base]                       = acc[mf][nf][0] + g_bias[n];
            g_preX[base + 1]                   = acc[mf][nf][1] + g_bias[n + 1];
            g_preX[base + 8 * (size_t)N4]      = acc[mf][nf][2] + g_bias[n];
            g_preX[base + 8 * (size_t)N4 + 1]  = acc[mf][nf][3] + g_bias[n + 1];
        }
    }
}

// ---------------- recurrent step (fused GEMM + LSTM cell) ----------------
// grid 64 CTAs x 256 thr; CTA owns 16 hidden units j0..j0+15 (all 4 gates => 64 N-cols)
// M=128, K=1024. Warp grid 4x2: warp tile 32m x 32n.
__global__ __launch_bounds__(256) void k_step(int t, int src, float* __restrict__ outs) {
    __shared__ float sbuf[128 * 68];   // union: (Hs 128x36 + Ws 64x36) | Ps 128x68
    float (*Hs)[36] = (float(*)[36])sbuf;
    float (*Ws)[36] = (float(*)[36])(sbuf + 128 * 36);
    float (*Ps)[68] = (float(*)[68])sbuf;

    const int tid  = threadIdx.x;
    const int lane = tid & 31;
    const int warp = tid >> 5;
    const int wm   = warp & 3;      // m offset 32
    const int wn   = warp >> 2;     // n offset 32
    const int j0   = blockIdx.x * 16;
    const int lr   = tid >> 3;      // 0..31
    const int lc   = (tid & 7) * 4; // 0..28
    const float* __restrict__ hsrc = g_h[src];

    float acc[2][4][4];
#pragma unroll
    for (int a = 0; a < 2; a++)
#pragma unroll
        for (int b = 0; b < 4; b++)
#pragma unroll
            for (int d = 0; d < 4; d++) acc[a][b][d] = 0.0f;

    float4 rh[4], rw[2];
#pragma unroll
    for (int p = 0; p < 4; p++)
        rh[p] = *(const float4*)&hsrc[(lr + p * 32) * DH + lc];
#pragma unroll
    for (int p = 0; p < 2; p++) {
        int c = lr + p * 32;
        int n = (c >> 4) * DH + j0 + (c & 15);
        rw[p] = *(const float4*)&g_Wh[(size_t)n * DH + lc];
    }

    for (int k0 = 0; k0 < DH; k0 += 32) {
#pragma unroll
        for (int p = 0; p < 4; p++) *(float4*)&Hs[lr + p * 32][lc] = rh[p];
#pragma unroll
        for (int p = 0; p < 2; p++) *(float4*)&Ws[lr + p * 32][lc] = rw[p];
        __syncthreads();
        int kn = k0 + 32;
        if (kn < DH) {
#pragma unroll
            for (int p = 0; p < 4; p++)
                rh[p] = *(const float4*)&hsrc[(lr + p * 32) * DH + kn + lc];
#pragma unroll
            for (int p = 0; p < 2; p++) {
                int c = lr + p * 32;
                int n = (c >> 4) * DH + j0 + (c & 15);
                rw[p] = *(const float4*)&g_Wh[(size_t)n * DH + kn + lc];
            }
        }
#pragma unroll
        for (int kk = 0; kk < 32; kk += 8) {
            uint32_t af[2][4];
            uint32_t bf[4][2];
#pragma unroll
            for (int mf = 0; mf < 2; mf++) {
                int rb0 = wm * 32 + mf * 16 + (lane >> 2);
                af[mf][0] = f2tf32(Hs[rb0][kk + (lane & 3)]);
                af[mf][1] = f2tf32(Hs[rb0 + 8][kk + (lane & 3)]);
                af[mf][2] = f2tf32(Hs[rb0][kk + 4 + (lane & 3)]);
                af[mf][3] = f2tf32(Hs[rb0 + 8][kk + 4 + (lane & 3)]);
            }
#pragma unroll
            for (int nf = 0; nf < 4; nf++) {
                int nb0 = wn * 32 + nf * 8 + (lane >> 2);
                bf[nf][0] = f2tf32(Ws[nb0][kk + (lane & 3)]);
                bf[nf][1] = f2tf32(Ws[nb0][kk + 4 + (lane & 3)]);
            }
#pragma unroll
            for (int mf = 0; mf < 2; mf++)
#pragma unroll
                for (int nf = 0; nf < 4; nf++)
                    mma_tf32(acc[mf][nf], af[mf], bf[nf]);
        }
        __syncthreads();   // also protects Ps aliasing below
    }

    // stage preactivations (pre_h + preX, bias already folded into preX) into Ps
#pragma unroll
    for (int mf = 0; mf < 2; mf++) {
#pragma unroll
        for (int nf = 0; nf < 4; nf++) {
            int r0 = wm * 32 + mf * 16 + (lane >> 2);
            int c0 = wn * 32 + nf * 8 + (lane & 3) * 2;
            int n0 = (c0 >> 4) * DH + j0 + (c0 & 15);
            size_t pb = ((size_t)t * NB + r0) * N4;
            Ps[r0][c0]         = acc[mf][nf][0] + g_preX[pb + n0];
            Ps[r0][c0 + 1]     = acc[mf][nf][1] + g_preX[pb + n0 + 1];
            Ps[r0 + 8][c0]     = acc[mf][nf][2] + g_preX[pb + 8 * (size_t)N4 + n0];
            Ps[r0 + 8][c0 + 1] = acc[mf][nf][3] + g_preX[pb + 8 * (size_t)N4 + n0 + 1];
        }
    }
    __syncthreads();

    // pointwise LSTM cell for this CTA's 16 hidden units
    float* hdst = g_h[src ^ 1];
    for (int e = tid; e < NB * 16; e += 256) {
        int b  = e >> 4;
        int jl = e & 15;
        float f  = fsigmoid(Ps[b][jl]);
        float ii = fsigmoid(Ps[b][16 + jl]);
        float gg = tanhf(Ps[b][32 + jl]);
        float oo = fsigmoid(Ps[b][48 + jl]);
        int j = j0 + jl;
        float cc = f * g_c[b * DH + j] + ii * gg;
        float hh = oo * tanhf(cc);
        g_c[b * DH + j]   = cc;
        hdst[b * DH + j]  = hh;
        outs[((size_t)t * NB + b) * DH + j] = hh;
    }
}

// ---------------- final h,c copy ----------------
__global__ void k_final(float* __restrict__ out) {
    int i = blockIdx.x * blockDim.x + threadIdx.x;
    if (i < NB * DH) {
        out[(size_t)TSTEPS * NB * DH + i]           = g_h[0][i];  // after 512 steps, h lives in buf 0
        out[(size_t)TSTEPS * NB * DH + NB * DH + i] = g_c[i];
    }
}

// ---------------- launch ----------------
extern "C" void kernel_launch(void* const* d_in, const int* in_sizes, int n_in,
                              void* d_out, int out_size) {
    const float* x  = (const float*)d_in[0];
    const float* h0 = (const float*)d_in[1];
    const float* c0 = (const float*)d_in[2];
    const float* Ax = (const float*)d_in[3];
    const float* Bx = (const float*)d_in[4];
    const float* Cx = (const float*)d_in[5];
    const float* Ah = (const float*)d_in[6];
    const float* Bh = (const float*)d_in[7];
    const float* Ch = (const float*)d_in[8];
    const float* bx = (const float*)d_in[9];
    const float* bh = (const float*)d_in[10];
    float* out = (float*)d_out;

    k_init<<<(NB * DH + 255) / 256, 256>>>(h0, c0);
    k_rich_bias<<<(4 * NR * DIN + 255) / 256, 256>>>(Ax, Ah, bx, bh);
    dim3 gs(DIN / 128, NSPAR / 8, 8);
    k_spar<<<gs, 128>>>(Bx, Cx, Bh, Ch);
    dim3 gx(N4 / 128, (TSTEPS * NB) / 128);
    k_xgemm<<<gx, 256>>>(x);
    for (int t = 0; t < TSTEPS; ++t)
        k_step<<<DH / 16, 256>>>(t, t & 1, out);
    k_final<<<(NB * DH + 255) / 256, 256>>>(out);
}

// round 3
// speedup vs baseline: 1.9700x; 1.9700x over previous
#include <cuda_runtime.h>
#include <cstdint>
#include <cstddef>

#define TSTEPS 512
#define NB     128        // batch
#define DIN    1024       // input size
#define DH     1024       // hidden
#define NR     256        // rank
#define N4     4096       // 4*DH
#define NSPAR  768        // DH-NR
#define RCTAS  128        // persistent CTAs
#define JW     8          // hidden units per CTA
#define NCOLS  32         // 4*JW gate-cols per CTA
#define KCH    32         // K chunk
#define NCHUNK (DH / KCH) // 32

// ---- static device scratch ----
__device__ float g_Wx[(size_t)N4 * DIN];                 // combined x weights [n][k]
__device__ float g_Wh[(size_t)N4 * DH];                  // combined h weights [n][k]
__device__ float g_bias[N4];
__device__ float g_preX[(size_t)TSTEPS * NB * N4];       // 1 GiB x-side preactivations (+bias)
__device__ float g_Whs[(size_t)RCTAS * DH * NCOLS];      // [cta][k][32] tf32-rounded
__device__ float g_h[2][NB * DH];                        // h ping-pong (tf32-rounded)
__device__ unsigned g_bar;

// ---------------- helpers ----------------
__device__ __forceinline__ uint32_t f2tf32(float f) {
    uint32_t u;
    asm("cvt.rna.tf32.f32 %0, %1;" : "=r"(u) : "f"(f));
    return u;
}
__device__ __forceinline__ float tf32r(float f) { return __uint_as_float(f2tf32(f)); }

__device__ __forceinline__ void mma_tf32(float* c, const uint32_t* a, const uint32_t* b) {
    asm volatile(
        "mma.sync.aligned.m16n8k8.row.col.f32.tf32.tf32.f32 "
        "{%0,%1,%2,%3}, {%4,%5,%6,%7}, {%8,%9}, {%0,%1,%2,%3};"
        : "+f"(c[0]), "+f"(c[1]), "+f"(c[2]), "+f"(c[3])
        : "r"(a[0]), "r"(a[1]), "r"(a[2]), "r"(a[3]), "r"(b[0]), "r"(b[1]));
}
__device__ __forceinline__ float fsigmoid(float x) { return 1.0f / (1.0f + __expf(-x)); }

__device__ __forceinline__ uint32_t smem_u32(const void* p) {
    uint32_t a;
    asm("{ .reg .u64 t; cvta.to.shared.u64 t, %1; cvt.u32.u64 %0, t; }" : "=r"(a) : "l"(p));
    return a;
}
__device__ __forceinline__ void cp16(uint32_t dst, const void* src) {
    asm volatile("cp.async.cg.shared.global [%0], [%1], 16;" :: "r"(dst), "l"(src));
}
__device__ __forceinline__ unsigned ld_acq(const unsigned* p) {
    unsigned v;
    asm volatile("ld.acquire.gpu.global.u32 %0, [%1];" : "=r"(v) : "l"(p) : "memory");
    return v;
}

// ---------------- init: rounded h0, reset barrier ----------------
__global__ void k_init(const float* __restrict__ h0) {
    int i = blockIdx.x * blockDim.x + threadIdx.x;
    if (i < NB * DH) g_h[0][i] = tf32r(h0[i]);
    if (i == 0) g_bar = 0;
}

// ---------------- rich rows (copy A) + bias ----------------
__global__ void k_rich_bias(const float* __restrict__ Ax, const float* __restrict__ Ah,
                            const float* __restrict__ bx, const float* __restrict__ bh) {
    int i = blockIdx.x * blockDim.x + threadIdx.x;
    if (i < 4 * NR * DIN) {
        int k = i % DIN;
        int row = i / DIN;
        int g = row / NR, j = row % NR;
        size_t w = ((size_t)(g * DH + j)) * DIN + k;
        g_Wx[w] = Ax[i];
        g_Wh[w] = Ah[i];
    }
    if (i < N4) g_bias[i] = bx[i] + bh[i];
}

// ---------------- sparse rows: W[g*DH+NR+m][k] = sum_r B[g][m][r]*C[g][r][k] ----------------
__global__ void k_spar(const float* __restrict__ Bx, const float* __restrict__ Cx,
                       const float* __restrict__ Bh, const float* __restrict__ Ch) {
    int z = blockIdx.z;
    int g = z & 3;
    const float* Bp = (z < 4) ? Bx : Bh;
    const float* Cp = (z < 4) ? Cx : Ch;
    float*       Wp = (z < 4) ? g_Wx : g_Wh;
    int m0  = blockIdx.y * 8;
    int col = blockIdx.x * 128 + threadIdx.x;

    __shared__ float Bs[8][NR];
    for (int i = threadIdx.x; i < 8 * NR; i += 128) {
        int mm = i / NR, rr = i % NR;
        Bs[mm][rr] = Bp[(size_t)(g * NSPAR + m0 + mm) * NR + rr];
    }
    __syncthreads();

    float acc[8];
#pragma unroll
    for (int mm = 0; mm < 8; mm++) acc[mm] = 0.0f;
    for (int r = 0; r < NR; ++r) {
        float cv = Cp[(size_t)(g * NR + r) * DIN + col];
#pragma unroll
        for (int mm = 0; mm < 8; mm++) acc[mm] += Bs[mm][r] * cv;
    }
#pragma unroll
    for (int mm = 0; mm < 8; mm++)
        Wp[(size_t)(g * DH + NR + m0 + mm) * DIN + col] = acc[mm];
}

// ---------------- pack Wh into per-CTA step layout [cta][k][32], tf32-rounded ----------------
__global__ void k_pack() {
    int i = blockIdx.x * blockDim.x + threadIdx.x;   // over 128*1024*32
    if (i >= RCTAS * DH * NCOLS) return;
    int col = i & 31;
    int k   = (i >> 5) & (DH - 1);
    int cta = i >> 15;
    int g  = col >> 3;
    int jl = col & 7;
    int n = g * DH + cta * JW + jl;
    g_Whs[i] = tf32r(g_Wh[(size_t)n * DH + k]);
}

// ---------------- X GEMM: preX = x @ Wx^T + bias (tf32 mma, unchanged from R0) ----------------
__global__ __launch_bounds__(256) void k_xgemm(const float* __restrict__ x) {
    __shared__ float As[128][36];
    __shared__ float Bs[128][36];
    const int tid  = threadIdx.x;
    const int lane = tid & 31;
    const int warp = tid >> 5;
    const int wm   = warp & 1;
    const int wn   = warp >> 1;
    const size_t mBase = (size_t)blockIdx.y * 128;
    const int    nBase = blockIdx.x * 128;
    const int lr = tid >> 3;
    const int lc = (tid & 7) * 4;

    float acc[4][4][4];
#pragma unroll
    for (int a = 0; a < 4; a++)
#pragma unroll
        for (int b = 0; b < 4; b++)
#pragma unroll
            for (int d = 0; d < 4; d++) acc[a][b][d] = 0.0f;

    float4 ra[4], rb[4];
#pragma unroll
    for (int p = 0; p < 4; p++) {
        int r = lr + p * 32;
        ra[p] = *(const float4*)&x[(mBase + r) * DIN + lc];
        rb[p] = *(const float4*)&g_Wx[((size_t)(nBase + r)) * DIN + lc];
    }

    for (int k0 = 0; k0 < DIN; k0 += 32) {
#pragma unroll
        for (int p = 0; p < 4; p++) {
            int r = lr + p * 32;
            *(float4*)&As[r][lc] = ra[p];
            *(float4*)&Bs[r][lc] = rb[p];
        }
        __syncthreads();
        int kn = k0 + 32;
        if (kn < DIN) {
#pragma unroll
            for (int p = 0; p < 4; p++) {
                int r = lr + p * 32;
                ra[p] = *(const float4*)&x[(mBase + r) * DIN + kn + lc];
                rb[p] = *(const float4*)&g_Wx[((size_t)(nBase + r)) * DIN + kn + lc];
            }
        }
#pragma unroll
        for (int kk = 0; kk < 32; kk += 8) {
            uint32_t af[4][4];
            uint32_t bf[4][2];
#pragma unroll
            for (int mf = 0; mf < 4; mf++) {
                int rb0 = wm * 64 + mf * 16 + (lane >> 2);
                af[mf][0] = f2tf32(As[rb0][kk + (lane & 3)]);
                af[mf][1] = f2tf32(As[rb0 + 8][kk + (lane & 3)]);
                af[mf][2] = f2tf32(As[rb0][kk + 4 + (lane & 3)]);
                af[mf][3] = f2tf32(As[rb0 + 8][kk + 4 + (lane & 3)]);
            }
#pragma unroll
            for (int nf = 0; nf < 4; nf++) {
                int nb0 = wn * 32 + nf * 8 + (lane >> 2);
                bf[nf][0] = f2tf32(Bs[nb0][kk + (lane & 3)]);
                bf[nf][1] = f2tf32(Bs[nb0][kk + 4 + (lane & 3)]);
            }
#pragma unroll
            for (int mf = 0; mf < 4; mf++)
#pragma unroll
                for (int nf = 0; nf < 4; nf++)
                    mma_tf32(acc[mf][nf], af[mf], bf[nf]);
        }
        __syncthreads();
    }

#pragma unroll
    for (int mf = 0; mf < 4; mf++) {
#pragma unroll
        for (int nf = 0; nf < 4; nf++) {
            int r0 = wm * 64 + mf * 16 + (lane >> 2);
            int c0 = wn * 32 + nf * 8 + (lane & 3) * 2;
            int n  = nBase + c0;
            size_t base = (mBase + r0) * (size_t)N4 + n;
            g_preX[base]                      = acc[mf][nf][0] + g_bias[n];
            g_preX[base + 1]                  = acc[mf][nf][1] + g_bias[n + 1];
            g_preX[base + 8 * (size_t)N4]     = acc[mf][nf][2] + g_bias[n];
            g_preX[base + 8 * (size_t)N4 + 1] = acc[mf][nf][3] + g_bias[n + 1];
        }
    }
}

// ---------------- persistent recurrence: all 512 steps in one kernel ----------------
// 128 CTAs x 256 thr; CTA owns 8 hidden units (32 gate-cols). M=128,N=32,K=1024 per step.
// 8 warps, each m16 x n32. Weights pre-rounded tf32 in g_Whs; h rounded at store.
__global__ __launch_bounds__(256) void k_rnn(const float* __restrict__ c0,
                                             float* __restrict__ out) {
    __shared__ float Hb[2][NB][36];    // h chunk double buffer [b][32k + pad]
    __shared__ float Wb[2][KCH][36];   // W chunk double buffer [k][32n + pad]

    const int tid  = threadIdx.x;
    const int lane = tid & 31;
    const int warp = tid >> 5;
    const int cta  = blockIdx.x;
    const int j0   = cta * JW;
    const int r0   = warp * 16 + (lane >> 2);   // batch row (and +8)
    const int q    = lane & 3;
    const int jl   = 2 * q;                      // local hidden unit (and +1)

    // cell state in registers: [row 0/8][jl 0/1]
    float cc[2][2];
    cc[0][0] = c0[(size_t)r0 * DH + j0 + jl];
    cc[0][1] = c0[(size_t)r0 * DH + j0 + jl + 1];
    cc[1][0] = c0[(size_t)(r0 + 8) * DH + j0 + jl];
    cc[1][1] = c0[(size_t)(r0 + 8) * DH + j0 + jl + 1];

    // precompute cp.async smem dst addresses pattern bases
    const uint32_t hb_base = smem_u32(&Hb[0][0][0]);
    const uint32_t wb_base = smem_u32(&Wb[0][0][0]);

    for (int t = 0; t < TSTEPS; ++t) {
        const int src = t & 1;
        const float* __restrict__ hsrc = g_h[src];

        // prefetch preX fragments (independent of h)
        float px[2][4][2];
        {
            size_t b0 = ((size_t)t * NB + r0) * N4 + j0 + jl;
            size_t b1 = b0 + 8 * (size_t)N4;
#pragma unroll
            for (int g = 0; g < 4; g++) {
                float2 v0 = *(const float2*)&g_preX[b0 + (size_t)g * DH];
                float2 v1 = *(const float2*)&g_preX[b1 + (size_t)g * DH];
                px[0][g][0] = v0.x; px[0][g][1] = v0.y;
                px[1][g][0] = v1.x; px[1][g][1] = v1.y;
            }
        }

        float acc[4][4];
#pragma unroll
        for (int a = 0; a < 4; a++)
#pragma unroll
            for (int b = 0; b < 4; b++) acc[a][b] = 0.0f;

        // issue chunk 0
        {
            const int k0 = 0, buf = 0;
            for (int s = tid; s < 1280; s += 256) {
                if (s < 1024) {
                    int b = s >> 3, seg = s & 7;
                    cp16(hb_base + (uint32_t)(buf * 18432 + b * 144 + seg * 16),
                         &hsrc[(size_t)b * DH + k0 + seg * 4]);
                } else {
                    int w = s - 1024;
                    int kl = w >> 3, seg = w & 7;
                    cp16(wb_base + (uint32_t)(buf * 4608 + kl * 144 + seg * 16),
                         &g_Whs[((size_t)cta * DH + k0 + kl) * NCOLS + seg * 4]);
                }
            }
            asm volatile("cp.async.commit_group;" ::: "memory");
        }

        for (int ch = 0; ch < NCHUNK; ++ch) {
            asm volatile("cp.async.wait_group 0;" ::: "memory");
            __syncthreads();   // chunk ch ready, prev compute done

            if (ch + 1 < NCHUNK) {
                const int k0 = (ch + 1) * KCH, buf = (ch + 1) & 1;
                for (int s = tid; s < 1280; s += 256) {
                    if (s < 1024) {
                        int b = s >> 3, seg = s & 7;
                        cp16(hb_base + (uint32_t)(buf * 18432 + b * 144 + seg * 16),
                             &hsrc[(size_t)b * DH + k0 + seg * 4]);
                    } else {
                        int w = s - 1024;
                        int kl = w >> 3, seg = w & 7;
                        cp16(wb_base + (uint32_t)(buf * 4608 + kl * 144 + seg * 16),
                             &g_Whs[((size_t)cta * DH + k0 + kl) * NCOLS + seg * 4]);
                    }
                }
                asm volatile("cp.async.commit_group;" ::: "memory");
            }

            const int cb = ch & 1;
#pragma unroll
            for (int kk = 0; kk < KCH; kk += 8) {
                uint32_t af[4];
                af[0] = __float_as_uint(Hb[cb][r0][kk + q]);
                af[1] = __float_as_uint(Hb[cb][r0 + 8][kk + q]);
                af[2] = __float_as_uint(Hb[cb][r0][kk + 4 + q]);
                af[3] = __float_as_uint(Hb[cb][r0 + 8][kk + 4 + q]);
#pragma unroll
                for (int nf = 0; nf < 4; nf++) {
                    uint32_t bf[2];
                    int nn = nf * 8 + (lane >> 2);
                    bf[0] = __float_as_uint(Wb[cb][kk + q][nn]);
                    bf[1] = __float_as_uint(Wb[cb][kk + 4 + q][nn]);
                    mma_tf32(acc[nf], af, bf);
                }
            }
        }

        // epilogue: pointwise LSTM in registers
        float* __restrict__ hdst = g_h[src ^ 1];
#pragma unroll
        for (int rr = 0; rr < 2; rr++) {
            int b = r0 + rr * 8;
            float hv[2];
#pragma unroll
            for (int w2 = 0; w2 < 2; w2++) {
                int i = rr * 2 + w2;
                float pf = acc[0][i] + px[rr][0][w2];
                float pi = acc[1][i] + px[rr][1][w2];
                float pg = acc[2][i] + px[rr][2][w2];
                float po = acc[3][i] + px[rr][3][w2];
                float f  = fsigmoid(pf);
                float ii = fsigmoid(pi);
                float gg = tanhf(pg);
                float oo = fsigmoid(po);
                float nc = f * cc[rr][w2] + ii * gg;
                hv[w2] = oo * tanhf(nc);
                cc[rr][w2] = nc;
            }
            float2 hfull = make_float2(hv[0], hv[1]);
            *(float2*)&out[((size_t)t * NB + b) * DH + j0 + jl] = hfull;
            float2 hr = make_float2(tf32r(hv[0]), tf32r(hv[1]));
            *(float2*)&hdst[(size_t)b * DH + j0 + jl] = hr;
            if (t == TSTEPS - 1) {
                *(float2*)&out[(size_t)TSTEPS * NB * DH + (size_t)b * DH + j0 + jl] = hfull;
                float2 cv = make_float2(cc[rr][0], cc[rr][1]);
                *(float2*)&out[(size_t)TSTEPS * NB * DH + (size_t)NB * DH + (size_t)b * DH + j0 + jl] = cv;
            }
        }

        // grid barrier (release h writes, acquire for next step)
        __threadfence();
        __syncthreads();
        if (tid == 0) {
            unsigned tgt = (unsigned)(t + 1) * RCTAS;
            atomicAdd(&g_bar, 1u);
            while (ld_acq(&g_bar) < tgt) { }
        }
        __syncthreads();
    }
}

// ---------------- launch ----------------
extern "C" void kernel_launch(void* const* d_in, const int* in_sizes, int n_in,
                              void* d_out, int out_size) {
    const float* x  = (const float*)d_in[0];
    const float* h0 = (const float*)d_in[1];
    const float* c0 = (const float*)d_in[2];
    const float* Ax = (const float*)d_in[3];
    const float* Bx = (const float*)d_in[4];
    const float* Cx = (const float*)d_in[5];
    const float* Ah = (const float*)d_in[6];
    const float* Bh = (const float*)d_in[7];
    const float* Ch = (const float*)d_in[8];
    const float* bx = (const float*)d_in[9];
    const float* bh = (const float*)d_in[10];
    float* out = (float*)d_out;

    k_init<<<(NB * DH + 255) / 256, 256>>>(h0);
    k_rich_bias<<<(4 * NR * DIN + 255) / 256, 256>>>(Ax, Ah, bx, bh);
    dim3 gs(DIN / 128, NSPAR / 8, 8);
    k_spar<<<gs, 128>>>(Bx, Cx, Bh, Ch);
    k_pack<<<(RCTAS * DH * NCOLS + 255) / 256, 256>>>();
    dim3 gx(N4 / 128, (TSTEPS * NB) / 128);
    k_xgemm<<<gx, 256>>>(x);
    k_rnn<<<RCTAS, 256>>>(c0, out);
}

// round 7
// speedup vs baseline: 2.2540x; 1.1441x over previous
#include <cuda_runtime.h>
#include <cstdint>
#include <cstddef>

#define TSTEPS 512
#define NB     128
#define DIN    1024
#define DH     1024
#define NR     256
#define N4     4096
#define NSPAR  768
#define RCTAS  128        // 64 N-tiles x 2 K-halves
#define KHALF  512
#define KCH    32
#define NCH    16         // KHALF/KCH
#define HROWF  36         // Hb row floats (pad)
#define WROWF  72         // Wb row floats (pad)
#define STG_BYTES (128 * HROWF * 4 + KCH * WROWF * 4)   // 18432 + 9216 = 27648

// ---- static device scratch ----
__device__ float g_Wx[(size_t)N4 * DIN];
__device__ float g_Wh[(size_t)N4 * DH];
__device__ float g_bias[N4];
__device__ float g_preX[(size_t)TSTEPS * NB * N4];          // 1 GiB
__device__ float g_Whs[(size_t)RCTAS * KHALF * 64];         // per-CTA K-half weights, tf32-rounded
__device__ float g_part[(size_t)64 * NB * 64];              // K-split partials per N-tile
__device__ unsigned g_pflag[64];
__device__ float g_h[2][NB * DH];                           // h ping-pong (tf32-rounded)
__device__ unsigned g_bar;

// ================= helpers =================
__device__ __forceinline__ uint32_t f2tf32(float f) {
    uint32_t u; asm("cvt.rna.tf32.f32 %0, %1;" : "=r"(u) : "f"(f)); return u;
}
__device__ __forceinline__ float tf32r(float f) { return __uint_as_float(f2tf32(f)); }

__device__ __forceinline__ void mma_tf32(float* c, const uint32_t* a, const uint32_t* b) {
    asm volatile("mma.sync.aligned.m16n8k8.row.col.f32.tf32.tf32.f32 "
                 "{%0,%1,%2,%3}, {%4,%5,%6,%7}, {%8,%9}, {%0,%1,%2,%3};"
                 : "+f"(c[0]), "+f"(c[1]), "+f"(c[2]), "+f"(c[3])
                 : "r"(a[0]), "r"(a[1]), "r"(a[2]), "r"(a[3]), "r"(b[0]), "r"(b[1]));
}
__device__ __forceinline__ float fsigmoid(float x) { return 1.0f / (1.0f + __expf(-x)); }

__device__ __forceinline__ uint32_t smem_u32(const void* p) {
    uint32_t a;
    asm("{ .reg .u64 t; cvta.to.shared.u64 t, %1; cvt.u32.u64 %0, t; }" : "=r"(a) : "l"(p));
    return a;
}
__device__ __forceinline__ void cp16(uint32_t dst, const void* src) {
    asm volatile("cp.async.cg.shared.global [%0], [%1], 16;" :: "r"(dst), "l"(src));
}
__device__ __forceinline__ unsigned ld_acq(const unsigned* p) {
    unsigned v;
    asm volatile("ld.acquire.gpu.global.u32 %0, [%1];" : "=r"(v) : "l"(p) : "memory");
    return v;
}
__device__ __forceinline__ void st_rel(unsigned* p, unsigned v) {
    asm volatile("st.release.gpu.global.u32 [%0], %1;" :: "l"(p), "r"(v) : "memory");
}
__device__ __forceinline__ float2 ldcg2(const float2* p) {
    float2 v;
    asm volatile("ld.global.cg.v2.f32 {%0,%1}, [%2];" : "=f"(v.x), "=f"(v.y) : "l"(p));
    return v;
}

// ================= prep kernels =================
__global__ void k_init(const float* __restrict__ h0) {
    int i = blockIdx.x * blockDim.x + threadIdx.x;
    if (i < NB * DH) g_h[0][i] = tf32r(h0[i]);
    if (i < 64) g_pflag[i] = 0;
    if (i == 0) g_bar = 0;
}

__global__ void k_rich_bias(const float* __restrict__ Ax, const float* __restrict__ Ah,
                            const float* __restrict__ bx, const float* __restrict__ bh) {
    int i = blockIdx.x * blockDim.x + threadIdx.x;
    if (i < 4 * NR * DIN) {
        int k = i % DIN, row = i / DIN;
        int g = row / NR, j = row % NR;
        size_t w = ((size_t)(g * DH + j)) * DIN + k;
        g_Wx[w] = Ax[i];
        g_Wh[w] = Ah[i];
    }
    if (i < N4) g_bias[i] = bx[i] + bh[i];
}

__global__ void k_spar(const float* __restrict__ Bx, const float* __restrict__ Cx,
                       const float* __restrict__ Bh, const float* __restrict__ Ch) {
    int z = blockIdx.z;
    int g = z & 3;
    const float* Bp = (z < 4) ? Bx : Bh;
    const float* Cp = (z < 4) ? Cx : Ch;
    float*       Wp = (z < 4) ? g_Wx : g_Wh;
    int m0  = blockIdx.y * 8;
    int col = blockIdx.x * 128 + threadIdx.x;

    __shared__ float Bs[8][NR];
    for (int i = threadIdx.x; i < 8 * NR; i += 128) {
        int mm = i / NR, rr = i % NR;
        Bs[mm][rr] = Bp[(size_t)(g * NSPAR + m0 + mm) * NR + rr];
    }
    __syncthreads();
    float acc[8];
#pragma unroll
    for (int mm = 0; mm < 8; mm++) acc[mm] = 0.0f;
    for (int r = 0; r < NR; ++r) {
        float cv = Cp[(size_t)(g * NR + r) * DIN + col];
#pragma unroll
        for (int mm = 0; mm < 8; mm++) acc[mm] += Bs[mm][r] * cv;
    }
#pragma unroll
    for (int mm = 0; mm < 8; mm++)
        Wp[(size_t)(g * DH + NR + m0 + mm) * DIN + col] = acc[mm];
}

// pack Wh -> [cta][k_local][64 cols], tf32-rounded. cta = khalf*64 + ntile; col = g*16+jl.
__global__ void k_pack() {
    int i = blockIdx.x * blockDim.x + threadIdx.x;    // 128*512*64 = 4,194,304
    if (i >= RCTAS * KHALF * 64) return;
    int col = i & 63;
    int kl  = (i >> 6) & (KHALF - 1);
    int cta = i >> 15;
    int ntile = cta & 63, khalf = cta >> 6;
    int n  = (col >> 4) * DH + ntile * 16 + (col & 15);
    int kg = khalf * KHALF + kl;
    g_Whs[i] = tf32r(g_Wh[(size_t)n * DH + kg]);
}

// ---------------- X GEMM: preX = x @ Wx^T + bias (tf32 mma.sync, unchanged) ----------------
__global__ __launch_bounds__(256) void k_xgemm(const float* __restrict__ x) {
    __shared__ float As[128][36];
    __shared__ float Bs[128][36];
    const int tid  = threadIdx.x;
    const int lane = tid & 31;
    const int warp = tid >> 5;
    const int wm   = warp & 1;
    const int wn   = warp >> 1;
    const size_t mBase = (size_t)blockIdx.y * 128;
    const int    nBase = blockIdx.x * 128;
    const int lr = tid >> 3;
    const int lc = (tid & 7) * 4;

    float acc[4][4][4];
#pragma unroll
    for (int a = 0; a < 4; a++)
#pragma unroll
        for (int b = 0; b < 4; b++)
#pragma unroll
            for (int d = 0; d < 4; d++) acc[a][b][d] = 0.0f;

    float4 ra[4], rb[4];
#pragma unroll
    for (int p = 0; p < 4; p++) {
        int r = lr + p * 32;
        ra[p] = *(const float4*)&x[(mBase + r) * DIN + lc];
        rb[p] = *(const float4*)&g_Wx[((size_t)(nBase + r)) * DIN + lc];
    }
    for (int k0 = 0; k0 < DIN; k0 += 32) {
#pragma unroll
        for (int p = 0; p < 4; p++) {
            int r = lr + p * 32;
            *(float4*)&As[r][lc] = ra[p];
            *(float4*)&Bs[r][lc] = rb[p];
        }
        __syncthreads();
        int kn = k0 + 32;
        if (kn < DIN) {
#pragma unroll
            for (int p = 0; p < 4; p++) {
                int r = lr + p * 32;
                ra[p] = *(const float4*)&x[(mBase + r) * DIN + kn + lc];
                rb[p] = *(const float4*)&g_Wx[((size_t)(nBase + r)) * DIN + kn + lc];
            }
        }
#pragma unroll
        for (int kk = 0; kk < 32; kk += 8) {
            uint32_t af[4][4];
            uint32_t bf[4][2];
#pragma unroll
            for (int mf = 0; mf < 4; mf++) {
                int rb0 = wm * 64 + mf * 16 + (lane >> 2);
                af[mf][0] = f2tf32(As[rb0][kk + (lane & 3)]);
                af[mf][1] = f2tf32(As[rb0 + 8][kk + (lane & 3)]);
                af[mf][2] = f2tf32(As[rb0][kk + 4 + (lane & 3)]);
                af[mf][3] = f2tf32(As[rb0 + 8][kk + 4 + (lane & 3)]);
            }
#pragma unroll
            for (int nf = 0; nf < 4; nf++) {
                int nb0 = wn * 32 + nf * 8 + (lane >> 2);
                bf[nf][0] = f2tf32(Bs[nb0][kk + (lane & 3)]);
                bf[nf][1] = f2tf32(Bs[nb0][kk + 4 + (lane & 3)]);
            }
#pragma unroll
            for (int mf = 0; mf < 4; mf++)
#pragma unroll
                for (int nf = 0; nf < 4; nf++)
                    mma_tf32(acc[mf][nf], af[mf], bf[nf]);
        }
        __syncthreads();
    }
#pragma unroll
    for (int mf = 0; mf < 4; mf++) {
#pragma unroll
        for (int nf = 0; nf < 4; nf++) {
            int r0 = wm * 64 + mf * 16 + (lane >> 2);
            int c0 = wn * 32 + nf * 8 + (lane & 3) * 2;
            int n  = nBase + c0;
            size_t base = (mBase + r0) * (size_t)N4 + n;
            g_preX[base]                      = acc[mf][nf][0] + g_bias[n];
            g_preX[base + 1]                  = acc[mf][nf][1] + g_bias[n + 1];
            g_preX[base + 8 * (size_t)N4]     = acc[mf][nf][2] + g_bias[n];
            g_preX[base + 8 * (size_t)N4 + 1] = acc[mf][nf][3] + g_bias[n + 1];
        }
    }
}

// ---------------- persistent K-split recurrence ----------------
// 128 CTAs x 256 thr. CTA = khalf*64 + ntile. Per step: acc[128,64] over its K-half,
// khalf1 ships partial to khalf0 via L2; khalf0 adds, does LSTM epilogue for its 16 units.
__global__ __launch_bounds__(256) void k_rnn(const float* __restrict__ c0,
                                             float* __restrict__ out) {
    extern __shared__ char dsm[];
    const int tid   = threadIdx.x;
    const int lane  = tid & 31;
    const int warp  = tid >> 5;
    const int cta   = blockIdx.x;
    const int ntile = cta & 63;
    const int khalf = cta >> 6;
    const int kbase = khalf * KHALF;
    const int wm    = warp & 1;        // m offset 0/64
    const int wn    = warp >> 1;       // n offset 0/16/32/48
    const int q     = lane & 3;
    float* Ps = (float*)dsm;           // [128][68] overlay (used after compute)

    const uint32_t dynb = smem_u32(dsm);

    // cell state: khalf0 warps 0-3, thread owns batch eb, 16 units
    float cst[16];
    const int eb = warp * 32 + lane;
    if (khalf == 0 && warp < 4) {
#pragma unroll
        for (int jl = 0; jl < 16; jl++) cst[jl] = c0[(size_t)eb * DH + ntile * 16 + jl];
    }

    for (int t = 0; t < TSTEPS; ++t) {
        const int src = t & 1;
        const float* __restrict__ hsrc = g_h[src];

        // ---- issue helper ----
        auto issue = [&](int cc) {
            uint32_t sb = dynb + (cc % 3) * STG_BYTES;
#pragma unroll
            for (int i = 0; i < 6; i++) {
                int s = tid + i * 256;            // 0..1535
                if (s < 1024) {
                    int r = s >> 3, seg = s & 7;
                    cp16(sb + (uint32_t)(r * 144 + seg * 16),
                         &hsrc[(size_t)r * DH + kbase + cc * KCH + seg * 4]);
                } else {
                    int v = s - 1024;             // 0..511
                    int k = v >> 4, seg = v & 15;
                    cp16(sb + (uint32_t)(18432 + k * 288 + seg * 16),
                         &g_Whs[(size_t)cta * (KHALF * 64) + (cc * KCH + k) * 64 + seg * 4]);
                }
            }
            asm volatile("cp.async.commit_group;" ::: "memory");
        };

        issue(0); issue(1); issue(2);

        float acc[4][2][4];
#pragma unroll
        for (int a = 0; a < 4; a++)
#pragma unroll
            for (int c = 0; c < 2; c++)
#pragma unroll
                for (int d = 0; d < 4; d++) acc[a][c][d] = 0.0f;

        for (int ch = 0; ch < NCH; ++ch) {
            if (ch < 14)       asm volatile("cp.async.wait_group 2;" ::: "memory");
            else if (ch == 14) asm volatile("cp.async.wait_group 1;" ::: "memory");
            else               asm volatile("cp.async.wait_group 0;" ::: "memory");
            __syncthreads();

            const float* Hs = (const float*)(dsm + (ch % 3) * STG_BYTES);
            const float* Ws = (const float*)(dsm + (ch % 3) * STG_BYTES + 18432);
#pragma unroll
            for (int kk = 0; kk < KCH; kk += 8) {
                uint32_t af[4][4];
#pragma unroll
                for (int mf = 0; mf < 4; mf++) {
                    int r0 = wm * 64 + mf * 16 + (lane >> 2);
                    af[mf][0] = __float_as_uint(Hs[r0 * HROWF + kk + q]);
                    af[mf][1] = __float_as_uint(Hs[(r0 + 8) * HROWF + kk + q]);
                    af[mf][2] = __float_as_uint(Hs[r0 * HROWF + kk + 4 + q]);
                    af[mf][3] = __float_as_uint(Hs[(r0 + 8) * HROWF + kk + 4 + q]);
                }
#pragma unroll
                for (int nf = 0; nf < 2; nf++) {
                    uint32_t bf[2];
                    int n0 = wn * 16 + nf * 8 + (lane >> 2);
                    bf[0] = __float_as_uint(Ws[(kk + q) * WROWF + n0]);
                    bf[1] = __float_as_uint(Ws[(kk + 4 + q) * WROWF + n0]);
#pragma unroll
                    for (int mf = 0; mf < 4; mf++)
                        mma_tf32(acc[mf][nf], af[mf], bf);
                }
            }
            __syncthreads();
            if (ch + 3 < NCH) issue(ch + 3);
        }

        if (khalf == 1) {
            // ship partial to the pair's khalf0 CTA
#pragma unroll
            for (int mf = 0; mf < 4; mf++) {
#pragma unroll
                for (int nf = 0; nf < 2; nf++) {
                    int r0 = wm * 64 + mf * 16 + (lane >> 2);
                    int c0i = wn * 16 + nf * 8 + q * 2;
                    size_t base = ((size_t)ntile * NB + r0) * 64 + c0i;
                    *(float2*)&g_part[base]          = make_float2(acc[mf][nf][0], acc[mf][nf][1]);
                    *(float2*)&g_part[base + 8 * 64] = make_float2(acc[mf][nf][2], acc[mf][nf][3]);
                }
            }
            __threadfence();
            __syncthreads();
            if (tid == 0) st_rel(&g_pflag[ntile], (unsigned)(t + 1));
        } else {
            // wait for the partial, merge, stage preacts into Ps
            if (tid == 0) {
                while (ld_acq(&g_pflag[ntile]) < (unsigned)(t + 1)) { }
            }
            __syncthreads();
#pragma unroll
            for (int mf = 0; mf < 4; mf++) {
#pragma unroll
                for (int nf = 0; nf < 2; nf++) {
                    int r0 = wm * 64 + mf * 16 + (lane >> 2);
                    int c0i = wn * 16 + nf * 8 + q * 2;
                    size_t base = ((size_t)ntile * NB + r0) * 64 + c0i;
                    float2 p0 = ldcg2((const float2*)&g_part[base]);
                    float2 p1 = ldcg2((const float2*)&g_part[base + 8 * 64]);
                    Ps[r0 * 68 + c0i]           = acc[mf][nf][0] + p0.x;
                    Ps[r0 * 68 + c0i + 1]       = acc[mf][nf][1] + p0.y;
                    Ps[(r0 + 8) * 68 + c0i]     = acc[mf][nf][2] + p1.x;
                    Ps[(r0 + 8) * 68 + c0i + 1] = acc[mf][nf][3] + p1.y;
                }
            }
            __syncthreads();

            if (warp < 4) {
                float* __restrict__ hdst = g_h[src ^ 1];
                size_t pxb = ((size_t)t * NB + eb) * N4 + ntile * 16;
                float hv[16];
#pragma unroll
                for (int qg = 0; qg < 4; qg++) {
                    int jl0 = qg * 4;
                    float4 p0 = *(const float4*)&g_preX[pxb + 0 * (size_t)DH + jl0];
                    float4 p1 = *(const float4*)&g_preX[pxb + 1 * (size_t)DH + jl0];
                    float4 p2 = *(const float4*)&g_preX[pxb + 2 * (size_t)DH + jl0];
                    float4 p3 = *(const float4*)&g_preX[pxb + 3 * (size_t)DH + jl0];
                    const float* pf = &p0.x;
                    const float* pi = &p1.x;
                    const float* pg = &p2.x;
                    const float* po = &p3.x;
#pragma unroll
                    for (int i = 0; i < 4; i++) {
                        int jl = jl0 + i;
                        float f  = fsigmoid(Ps[eb * 68 + jl]      + pf[i]);
                        float ii = fsigmoid(Ps[eb * 68 + 16 + jl] + pi[i]);
                        float gg = tanhf(Ps[eb * 68 + 32 + jl]    + pg[i]);
                        float oo = fsigmoid(Ps[eb * 68 + 48 + jl] + po[i]);
                        float nc = f * cst[jl] + ii * gg;
                        cst[jl] = nc;
                        hv[jl] = oo * tanhf(nc);
                    }
                    *(float4*)&out[((size_t)t * NB + eb) * DH + ntile * 16 + jl0] =
                        make_float4(hv[jl0], hv[jl0 + 1], hv[jl0 + 2], hv[jl0 + 3]);
                    *(float4*)&hdst[(size_t)eb * DH + ntile * 16 + jl0] =
                        make_float4(tf32r(hv[jl0]), tf32r(hv[jl0 + 1]),
                                    tf32r(hv[jl0 + 2]), tf32r(hv[jl0 + 3]));
                }
                if (t == TSTEPS - 1) {
#pragma unroll
                    for (int qg = 0; qg < 4; qg++) {
                        int jl0 = qg * 4;
                        *(float4*)&out[(size_t)TSTEPS * NB * DH + (size_t)eb * DH + ntile * 16 + jl0] =
                            make_float4(hv[jl0], hv[jl0 + 1], hv[jl0 + 2], hv[jl0 + 3]);
                        *(float4*)&out[(size_t)TSTEPS * NB * DH + (size_t)NB * DH + (size_t)eb * DH + ntile * 16 + jl0] =
                            make_float4(cst[jl0], cst[jl0 + 1], cst[jl0 + 2], cst[jl0 + 3]);
                    }
                }
            }
        }

        // global step barrier
        __threadfence();
        __syncthreads();
        if (tid == 0) {
            unsigned tgt = (unsigned)(t + 1) * RCTAS;
            atomicAdd(&g_bar, 1u);
            while (ld_acq(&g_bar) < tgt) { }
        }
        __syncthreads();
    }
}

// ---------------- launch ----------------
extern "C" void kernel_launch(void* const* d_in, const int* in_sizes, int n_in,
                              void* d_out, int out_size) {
    const float* x  = (const float*)d_in[0];
    const float* h0 = (const float*)d_in[1];
    const float* c0 = (const float*)d_in[2];
    const float* Ax = (const float*)d_in[3];
    const float* Bx = (const float*)d_in[4];
    const float* Cx = (const float*)d_in[5];
    const float* Ah = (const float*)d_in[6];
    const float* Bh = (const float*)d_in[7];
    const float* Ch = (const float*)d_in[8];
    const float* bx = (const float*)d_in[9];
    const float* bh = (const float*)d_in[10];
    float* out = (float*)d_out;

    const int smem_bytes = 3 * STG_BYTES;     // 82944
    cudaFuncSetAttribute(k_rnn, cudaFuncAttributeMaxDynamicSharedMemorySize, smem_bytes);

    k_init<<<(NB * DH + 255) / 256, 256>>>(h0);
    k_rich_bias<<<(4 * NR * DIN + 255) / 256, 256>>>(Ax, Ah, bx, bh);
    dim3 gs(DIN / 128, NSPAR / 8, 8);
    k_spar<<<gs, 128>>>(Bx, Cx, Bh, Ch);
    k_pack<<<(RCTAS * KHALF * 64 + 255) / 256, 256>>>();
    dim3 gx(N4 / 128, (TSTEPS * NB) / 128);
    k_xgemm<<<gx, 256>>>(x);
    k_rnn<<<RCTAS, 256, smem_bytes>>>(c0, out);
}

// round 8
// speedup vs baseline: 2.9238x; 1.2972x over previous
#include <cuda_runtime.h>
#include <cstdint>
#include <cstddef>

#define TSTEPS 512
#define NB     128
#define DIN    1024
#define DH     1024
#define NR     256
#define N4     4096
#define NSPAR  768
#define RCTAS  128        // 2 batch-halves x 64 N-tiles
#define KCH    128
#define NCH    8          // DH/KCH
#define HROWF  132        // Hb row floats (128 + 4 pad)
#define WROWF  72         // Wb row floats (64 + 8 pad)
#define STG_BYTES (64 * HROWF * 4 + KCH * WROWF * 4)   // 33792 + 36864 = 70656

// ---- static device scratch ----
__device__ float g_Wx[(size_t)N4 * DIN];
__device__ float g_Wh[(size_t)N4 * DH];
__device__ float g_bias[N4];
__device__ float g_preX[(size_t)TSTEPS * NB * N4];          // 1 GiB
__device__ float g_Whs[(size_t)64 * DH * 64];               // [ntile][k][64], tf32-rounded
__device__ float g_h[2][NB * DH];                           // h ping-pong (tf32-rounded)
__device__ unsigned g_barg[8];
__device__ unsigned g_root;

// ================= helpers =================
__device__ __forceinline__ uint32_t f2tf32(float f) {
    uint32_t u; asm("cvt.rna.tf32.f32 %0, %1;" : "=r"(u) : "f"(f)); return u;
}
__device__ __forceinline__ float tf32r(float f) { return __uint_as_float(f2tf32(f)); }

__device__ __forceinline__ void mma_tf32(float* c, const uint32_t* a, const uint32_t* b) {
    asm volatile("mma.sync.aligned.m16n8k8.row.col.f32.tf32.tf32.f32 "
                 "{%0,%1,%2,%3}, {%4,%5,%6,%7}, {%8,%9}, {%0,%1,%2,%3};"
                 : "+f"(c[0]), "+f"(c[1]), "+f"(c[2]), "+f"(c[3])
                 : "r"(a[0]), "r"(a[1]), "r"(a[2]), "r"(a[3]), "r"(b[0]), "r"(b[1]));
}
__device__ __forceinline__ float fsigmoid(float x) { return 1.0f / (1.0f + __expf(-x)); }

__device__ __forceinline__ uint32_t smem_u32(const void* p) {
    uint32_t a;
    asm("{ .reg .u64 t; cvta.to.shared.u64 t, %1; cvt.u32.u64 %0, t; }" : "=r"(a) : "l"(p));
    return a;
}
__device__ __forceinline__ void cp16(uint32_t dst, const void* src) {
    asm volatile("cp.async.cg.shared.global [%0], [%1], 16;" :: "r"(dst), "l"(src));
}
__device__ __forceinline__ unsigned ld_acq(const unsigned* p) {
    unsigned v;
    asm volatile("ld.acquire.gpu.global.u32 %0, [%1];" : "=r"(v) : "l"(p) : "memory");
    return v;
}

// ================= prep kernels =================
__global__ void k_init(const float* __restrict__ h0) {
    int i = blockIdx.x * blockDim.x + threadIdx.x;
    if (i < NB * DH) g_h[0][i] = tf32r(h0[i]);
    if (i < 8) g_barg[i] = 0;
    if (i == 0) g_root = 0;
}

__global__ void k_rich_bias(const float* __restrict__ Ax, const float* __restrict__ Ah,
                            const float* __restrict__ bx, const float* __restrict__ bh) {
    int i = blockIdx.x * blockDim.x + threadIdx.x;
    if (i < 4 * NR * DIN) {
        int k = i % DIN, row = i / DIN;
        int g = row / NR, j = row % NR;
        size_t w = ((size_t)(g * DH + j)) * DIN + k;
        g_Wx[w] = Ax[i];
        g_Wh[w] = Ah[i];
    }
    if (i < N4) g_bias[i] = bx[i] + bh[i];
}

__global__ void k_spar(const float* __restrict__ Bx, const float* __restrict__ Cx,
                       const float* __restrict__ Bh, const float* __restrict__ Ch) {
    int z = blockIdx.z;
    int g = z & 3;
    const float* Bp = (z < 4) ? Bx : Bh;
    const float* Cp = (z < 4) ? Cx : Ch;
    float*       Wp = (z < 4) ? g_Wx : g_Wh;
    int m0  = blockIdx.y * 8;
    int col = blockIdx.x * 128 + threadIdx.x;

    __shared__ float Bs[8][NR];
    for (int i = threadIdx.x; i < 8 * NR; i += 128) {
        int mm = i / NR, rr = i % NR;
        Bs[mm][rr] = Bp[(size_t)(g * NSPAR + m0 + mm) * NR + rr];
    }
    __syncthreads();
    float acc[8];
#pragma unroll
    for (int mm = 0; mm < 8; mm++) acc[mm] = 0.0f;
    for (int r = 0; r < NR; ++r) {
        float cv = Cp[(size_t)(g * NR + r) * DIN + col];
#pragma unroll
        for (int mm = 0; mm < 8; mm++) acc[mm] += Bs[mm][r] * cv;
    }
#pragma unroll
    for (int mm = 0; mm < 8; mm++)
        Wp[(size_t)(g * DH + NR + m0 + mm) * DIN + col] = acc[mm];
}

// pack Wh -> [ntile][k][64 cols], tf32-rounded. col = g*16 + jl.
__global__ void k_pack() {
    int i = blockIdx.x * blockDim.x + threadIdx.x;     // 64*1024*64 = 4,194,304
    if (i >= 64 * DH * 64) return;
    int col   = i & 63;
    int k     = (i >> 6) & (DH - 1);
    int ntile = i >> 16;
    int n = (col >> 4) * DH + ntile * 16 + (col & 15);
    g_Whs[i] = tf32r(g_Wh[(size_t)n * DH + k]);
}

// ---------------- X GEMM: preX = x @ Wx^T + bias (tf32 mma.sync, unchanged) ----------------
__global__ __launch_bounds__(256) void k_xgemm(const float* __restrict__ x) {
    __shared__ float As[128][36];
    __shared__ float Bs[128][36];
    const int tid  = threadIdx.x;
    const int lane = tid & 31;
    const int warp = tid >> 5;
    const int wm   = warp & 1;
    const int wn   = warp >> 1;
    const size_t mBase = (size_t)blockIdx.y * 128;
    const int    nBase = blockIdx.x * 128;
    const int lr = tid >> 3;
    const int lc = (tid & 7) * 4;

    float acc[4][4][4];
#pragma unroll
    for (int a = 0; a < 4; a++)
#pragma unroll
        for (int b = 0; b < 4; b++)
#pragma unroll
            for (int d = 0; d < 4; d++) acc[a][b][d] = 0.0f;

    float4 ra[4], rb[4];
#pragma unroll
    for (int p = 0; p < 4; p++) {
        int r = lr + p * 32;
        ra[p] = *(const float4*)&x[(mBase + r) * DIN + lc];
        rb[p] = *(const float4*)&g_Wx[((size_t)(nBase + r)) * DIN + lc];
    }
    for (int k0 = 0; k0 < DIN; k0 += 32) {
#pragma unroll
        for (int p = 0; p < 4; p++) {
            int r = lr + p * 32;
            *(float4*)&As[r][lc] = ra[p];
            *(float4*)&Bs[r][lc] = rb[p];
        }
        __syncthreads();
        int kn = k0 + 32;
        if (kn < DIN) {
#pragma unroll
            for (int p = 0; p < 4; p++) {
                int r = lr + p * 32;
                ra[p] = *(const float4*)&x[(mBase + r) * DIN + kn + lc];
                rb[p] = *(const float4*)&g_Wx[((size_t)(nBase + r)) * DIN + kn + lc];
            }
        }
#pragma unroll
        for (int kk = 0; kk < 32; kk += 8) {
            uint32_t af[4][4];
            uint32_t bf[4][2];
#pragma unroll
            for (int mf = 0; mf < 4; mf++) {
                int rb0 = wm * 64 + mf * 16 + (lane >> 2);
                af[mf][0] = f2tf32(As[rb0][kk + (lane & 3)]);
                af[mf][1] = f2tf32(As[rb0 + 8][kk + (lane & 3)]);
                af[mf][2] = f2tf32(As[rb0][kk + 4 + (lane & 3)]);
                af[mf][3] = f2tf32(As[rb0 + 8][kk + 4 + (lane & 3)]);
            }
#pragma unroll
            for (int nf = 0; nf < 4; nf++) {
                int nb0 = wn * 32 + nf * 8 + (lane >> 2);
                bf[nf][0] = f2tf32(Bs[nb0][kk + (lane & 3)]);
                bf[nf][1] = f2tf32(Bs[nb0][kk + 4 + (lane & 3)]);
            }
#pragma unroll
            for (int mf = 0; mf < 4; mf++)
#pragma unroll
                for (int nf = 0; nf < 4; nf++)
                    mma_tf32(acc[mf][nf], af[mf], bf[nf]);
        }
        __syncthreads();
    }
#pragma unroll
    for (int mf = 0; mf < 4; mf++) {
#pragma unroll
        for (int nf = 0; nf < 4; nf++) {
            int r0 = wm * 64 + mf * 16 + (lane >> 2);
            int c0 = wn * 32 + nf * 8 + (lane & 3) * 2;
            int n  = nBase + c0;
            size_t base = (mBase + r0) * (size_t)N4 + n;
            g_preX[base]                      = acc[mf][nf][0] + g_bias[n];
            g_preX[base + 1]                  = acc[mf][nf][1] + g_bias[n + 1];
            g_preX[base + 8 * (size_t)N4]     = acc[mf][nf][2] + g_bias[n];
            g_preX[base + 8 * (size_t)N4 + 1] = acc[mf][nf][3] + g_bias[n + 1];
        }
    }
}

// ---------------- persistent M-split recurrence ----------------
// 128 CTAs x 256 thr. CTA = bhalf*64 + ntile: M=64 batch rows, N=64 gate-cols, K=1024.
// 8 warps: 4 tile positions (32m x 32n) x 2 K-interleave groups; merge via smem; own epilogue.
__global__ __launch_bounds__(256) void k_rnn(const float* __restrict__ c0,
                                             float* __restrict__ out) {
    extern __shared__ char dsm[];
    const int tid   = threadIdx.x;
    const int lane  = tid & 31;
    const int warp  = tid >> 5;
    const int cta   = blockIdx.x;
    const int ntile = cta & 63;
    const int bhalf = cta >> 6;
    const int bh64  = bhalf * 64;
    const int wq    = warp & 3;        // tile position
    const int kpar  = warp >> 2;       // K-interleave group
    const int wm    = wq & 1;          // m offset 0/32
    const int wn    = wq >> 1;         // n offset 0/32
    const int q     = lane & 3;
    float* Ps = (float*)dsm;           // [64][68] overlay after compute

    const uint32_t dynb = smem_u32(dsm);

    // epilogue ownership: row r = tid&63 (batch bh64+r), unit group ug = tid>>6 (4 units)
    const int er = tid & 63;
    const int ug = tid >> 6;
    const int eb = bh64 + er;

    float cst[4];
    {
        float4 cv = *(const float4*)&c0[(size_t)eb * DH + ntile * 16 + ug * 4];
        cst[0] = cv.x; cst[1] = cv.y; cst[2] = cv.z; cst[3] = cv.w;
    }

    for (int t = 0; t < TSTEPS; ++t) {
        const int src = t & 1;
        const float* __restrict__ hsrc = g_h[src];

        auto issue = [&](int cc) {
            uint32_t sb = dynb + (cc % 3) * STG_BYTES;
#pragma unroll
            for (int i = 0; i < 16; i++) {
                int s = tid + i * 256;              // 0..4095
                if (s < 2048) {
                    int r = s >> 5, seg = s & 31;
                    cp16(sb + (uint32_t)(r * (HROWF * 4) + seg * 16),
                         &hsrc[(size_t)(bh64 + r) * DH + cc * KCH + seg * 4]);
                } else {
                    int v = s - 2048;               // 0..2047
                    int kl = v >> 4, seg = v & 15;
                    cp16(sb + (uint32_t)(64 * HROWF * 4 + kl * (WROWF * 4) + seg * 16),
                         &g_Whs[(size_t)ntile * (DH * 64) + (cc * KCH + kl) * 64 + seg * 4]);
                }
            }
            asm volatile("cp.async.commit_group;" ::: "memory");
        };

        issue(0); issue(1); issue(2);

        // prefetch preX for this thread's epilogue slice (independent of h)
        float4 px[4];
        {
            size_t pxb = ((size_t)t * NB + eb) * N4 + ntile * 16 + ug * 4;
#pragma unroll
            for (int g = 0; g < 4; g++)
                px[g] = *(const float4*)&g_preX[pxb + (size_t)g * DH];
        }

        float acc[2][4][4];
#pragma unroll
        for (int a = 0; a < 2; a++)
#pragma unroll
            for (int c = 0; c < 4; c++)
#pragma unroll
                for (int d = 0; d < 4; d++) acc[a][c][d] = 0.0f;

        for (int ch = 0; ch < NCH; ++ch) {
            if (ch < NCH - 2)       asm volatile("cp.async.wait_group 2;" ::: "memory");
            else if (ch == NCH - 2) asm volatile("cp.async.wait_group 1;" ::: "memory");
            else                    asm volatile("cp.async.wait_group 0;" ::: "memory");
            __syncthreads();

            const float* Hs = (const float*)(dsm + (ch % 3) * STG_BYTES);
            const float* Ws = (const float*)(dsm + (ch % 3) * STG_BYTES + 64 * HROWF * 4);
#pragma unroll
            for (int k8 = 0; k8 < 16; k8 += 2) {
                int kk = (k8 + kpar) * 8;
                uint32_t af[2][4];
#pragma unroll
                for (int mf = 0; mf < 2; mf++) {
                    int r0 = wm * 32 + mf * 16 + (lane >> 2);
                    af[mf][0] = __float_as_uint(Hs[r0 * HROWF + kk + q]);
                    af[mf][1] = __float_as_uint(Hs[(r0 + 8) * HROWF + kk + q]);
                    af[mf][2] = __float_as_uint(Hs[r0 * HROWF + kk + 4 + q]);
                    af[mf][3] = __float_as_uint(Hs[(r0 + 8) * HROWF + kk + 4 + q]);
                }
#pragma unroll
                for (int nf = 0; nf < 4; nf++) {
                    uint32_t bf[2];
                    int n0 = wn * 32 + nf * 8 + (lane >> 2);
                    bf[0] = __float_as_uint(Ws[(kk + q) * WROWF + n0]);
                    bf[1] = __float_as_uint(Ws[(kk + 4 + q) * WROWF + n0]);
#pragma unroll
                    for (int mf = 0; mf < 2; mf++)
                        mma_tf32(acc[mf][nf], af[mf], bf);
                }
            }
            __syncthreads();
            if (ch + 3 < NCH) issue(ch + 3);
        }

        // merge K-interleave halves through Ps, then epilogue
        if (kpar == 1) {
#pragma unroll
            for (int mf = 0; mf < 2; mf++) {
#pragma unroll
                for (int nf = 0; nf < 4; nf++) {
                    int r0 = wm * 32 + mf * 16 + (lane >> 2);
                    int c0i = wn * 32 + nf * 8 + q * 2;
                    Ps[r0 * 68 + c0i]           = acc[mf][nf][0];
                    Ps[r0 * 68 + c0i + 1]       = acc[mf][nf][1];
                    Ps[(r0 + 8) * 68 + c0i]     = acc[mf][nf][2];
                    Ps[(r0 + 8) * 68 + c0i + 1] = acc[mf][nf][3];
                }
            }
        }
        __syncthreads();
        if (kpar == 0) {
#pragma unroll
            for (int mf = 0; mf < 2; mf++) {
#pragma unroll
                for (int nf = 0; nf < 4; nf++) {
                    int r0 = wm * 32 + mf * 16 + (lane >> 2);
                    int c0i = wn * 32 + nf * 8 + q * 2;
                    Ps[r0 * 68 + c0i]           += acc[mf][nf][0];
                    Ps[r0 * 68 + c0i + 1]       += acc[mf][nf][1];
                    Ps[(r0 + 8) * 68 + c0i]     += acc[mf][nf][2];
                    Ps[(r0 + 8) * 68 + c0i + 1] += acc[mf][nf][3];
                }
            }
        }
        __syncthreads();

        // pointwise LSTM: thread -> (row er, units ug*4..+3)
        {
            float* __restrict__ hdst = g_h[src ^ 1];
            float hv[4];
#pragma unroll
            for (int i = 0; i < 4; i++) {
                int jc = ug * 4 + i;
                float f  = fsigmoid(Ps[er * 68 + jc]      + ((const float*)&px[0])[i]);
                float ii = fsigmoid(Ps[er * 68 + 16 + jc] + ((const float*)&px[1])[i]);
                float gg = tanhf(Ps[er * 68 + 32 + jc]    + ((const float*)&px[2])[i]);
                float oo = fsigmoid(Ps[er * 68 + 48 + jc] + ((const float*)&px[3])[i]);
                float nc = f * cst[i] + ii * gg;
                cst[i] = nc;
                hv[i] = oo * tanhf(nc);
            }
            size_t oo = ((size_t)t * NB + eb) * DH + ntile * 16 + ug * 4;
            *(float4*)&out[oo] = make_float4(hv[0], hv[1], hv[2], hv[3]);
            *(float4*)&hdst[(size_t)eb * DH + ntile * 16 + ug * 4] =
                make_float4(tf32r(hv[0]), tf32r(hv[1]), tf32r(hv[2]), tf32r(hv[3]));
            if (t == TSTEPS - 1) {
                size_t fb = (size_t)TSTEPS * NB * DH + (size_t)eb * DH + ntile * 16 + ug * 4;
                *(float4*)&out[fb] = make_float4(hv[0], hv[1], hv[2], hv[3]);
                *(float4*)&out[fb + (size_t)NB * DH] = make_float4(cst[0], cst[1], cst[2], cst[3]);
            }
        }

        // two-level tree barrier
        __threadfence();
        __syncthreads();
        if (tid == 0) {
            unsigned r = atomicAdd(&g_barg[cta >> 4], 1u);
            if (r == 16u * (unsigned)(t + 1) - 1u) {
                __threadfence();
                atomicAdd(&g_root, 1u);
            }
            while (ld_acq(&g_root) < 8u * (unsigned)(t + 1)) { }
        }
        __syncthreads();
    }
}

// ---------------- launch ----------------
extern "C" void kernel_launch(void* const* d_in, const int* in_sizes, int n_in,
                              void* d_out, int out_size) {
    const float* x  = (const float*)d_in[0];
    const float* h0 = (const float*)d_in[1];
    const float* c0 = (const float*)d_in[2];
    const float* Ax = (const float*)d_in[3];
    const float* Bx = (const float*)d_in[4];
    const float* Cx = (const float*)d_in[5];
    const float* Ah = (const float*)d_in[6];
    const float* Bh = (const float*)d_in[7];
    const float* Ch = (const float*)d_in[8];
    const float* bx = (const float*)d_in[9];
    const float* bh = (const float*)d_in[10];
    float* out = (float*)d_out;

    const int smem_bytes = 3 * STG_BYTES;     // 211968
    cudaFuncSetAttribute(k_rnn, cudaFuncAttributeMaxDynamicSharedMemorySize, smem_bytes);

    k_init<<<(NB * DH + 255) / 256, 256>>>(h0);
    k_rich_bias<<<(4 * NR * DIN + 255) / 256, 256>>>(Ax, Ah, bx, bh);
    dim3 gs(DIN / 128, NSPAR / 8, 8);
    k_spar<<<gs, 128>>>(Bx, Cx, Bh, Ch);
    k_pack<<<(64 * DH * 64 + 255) / 256, 256>>>();
    dim3 gx(N4 / 128, (TSTEPS * NB) / 128);
    k_xgemm<<<gx, 256>>>(x);
    k_rnn<<<RCTAS, 256, smem_bytes>>>(c0, out);
}

// round 9
// speedup vs baseline: 3.6311x; 1.2419x over previous
#include <cuda_runtime.h>
#include <cuda_fp16.h>
#include <cstdint>
#include <cstddef>

#define TSTEPS 512
#define NB     128
#define DIN    1024
#define DH     1024
#define NR     256
#define N4     4096
#define NSPAR  768
#define RCTAS  128        // 2 batch-halves x 64 N-tiles
#define KCH    128
#define NCH    8          // DH/KCH
#define HSTRB  272        // Hs row stride bytes (256 data + 16 pad) -> 68 banks
#define WSTRB  288        // Ws k-pair row stride bytes (256 data + 32 pad) -> 72 banks
#define STG_BYTES (64 * HSTRB + 64 * WSTRB)    // 17408 + 18432 = 35840

// ---- static device scratch ----
__device__ float g_Wx[(size_t)N4 * DIN];
__device__ float g_Wh[(size_t)N4 * DH];
__device__ float g_bias[N4];
__device__ float g_preX[(size_t)TSTEPS * NB * N4];          // 1 GiB
__device__ __half g_Whs[(size_t)64 * 512 * 128];            // [ntile][kpair][n*2+par] fp16
__device__ __half g_h[2][NB * DH];                          // h ping-pong (fp16)
__device__ unsigned g_barg[8];
__device__ unsigned g_root;

// ================= helpers =================
__device__ __forceinline__ uint32_t f2tf32(float f) {
    uint32_t u; asm("cvt.rna.tf32.f32 %0, %1;" : "=r"(u) : "f"(f)); return u;
}

__device__ __forceinline__ void mma_tf32(float* c, const uint32_t* a, const uint32_t* b) {
    asm volatile("mma.sync.aligned.m16n8k8.row.col.f32.tf32.tf32.f32 "
                 "{%0,%1,%2,%3}, {%4,%5,%6,%7}, {%8,%9}, {%0,%1,%2,%3};"
                 : "+f"(c[0]), "+f"(c[1]), "+f"(c[2]), "+f"(c[3])
                 : "r"(a[0]), "r"(a[1]), "r"(a[2]), "r"(a[3]), "r"(b[0]), "r"(b[1]));
}
__device__ __forceinline__ void mma_f16(float* c, const uint32_t* a, const uint32_t* b) {
    asm volatile("mma.sync.aligned.m16n8k16.row.col.f32.f16.f16.f32 "
                 "{%0,%1,%2,%3}, {%4,%5,%6,%7}, {%8,%9}, {%0,%1,%2,%3};"
                 : "+f"(c[0]), "+f"(c[1]), "+f"(c[2]), "+f"(c[3])
                 : "r"(a[0]), "r"(a[1]), "r"(a[2]), "r"(a[3]), "r"(b[0]), "r"(b[1]));
}
__device__ __forceinline__ float fsigmoid(float x) { return 1.0f / (1.0f + __expf(-x)); }

__device__ __forceinline__ uint32_t smem_u32(const void* p) {
    uint32_t a;
    asm("{ .reg .u64 t; cvta.to.shared.u64 t, %1; cvt.u32.u64 %0, t; }" : "=r"(a) : "l"(p));
    return a;
}
__device__ __forceinline__ void cp16(uint32_t dst, const void* src) {
    asm volatile("cp.async.cg.shared.global [%0], [%1], 16;" :: "r"(dst), "l"(src));
}
__device__ __forceinline__ unsigned ld_acq(const unsigned* p) {
    unsigned v;
    asm volatile("ld.acquire.gpu.global.u32 %0, [%1];" : "=r"(v) : "l"(p) : "memory");
    return v;
}

// ================= prep kernels =================
__global__ void k_init(const float* __restrict__ h0) {
    int i = blockIdx.x * blockDim.x + threadIdx.x;
    if (i < NB * DH) g_h[0][i] = __float2half_rn(h0[i]);
    if (i < 8) g_barg[i] = 0;
    if (i == 0) g_root = 0;
}

__global__ void k_rich_bias(const float* __restrict__ Ax, const float* __restrict__ Ah,
                            const float* __restrict__ bx, const float* __restrict__ bh) {
    int i = blockIdx.x * blockDim.x + threadIdx.x;
    if (i < 4 * NR * DIN) {
        int k = i % DIN, row = i / DIN;
        int g = row / NR, j = row % NR;
        size_t w = ((size_t)(g * DH + j)) * DIN + k;
        g_Wx[w] = Ax[i];
        g_Wh[w] = Ah[i];
    }
    if (i < N4) g_bias[i] = bx[i] + bh[i];
}

__global__ void k_spar(const float* __restrict__ Bx, const float* __restrict__ Cx,
                       const float* __restrict__ Bh, const float* __restrict__ Ch) {
    int z = blockIdx.z;
    int g = z & 3;
    const float* Bp = (z < 4) ? Bx : Bh;
    const float* Cp = (z < 4) ? Cx : Ch;
    float*       Wp = (z < 4) ? g_Wx : g_Wh;
    int m0  = blockIdx.y * 8;
    int col = blockIdx.x * 128 + threadIdx.x;

    __shared__ float Bs[8][NR];
    for (int i = threadIdx.x; i < 8 * NR; i += 128) {
        int mm = i / NR, rr = i % NR;
        Bs[mm][rr] = Bp[(size_t)(g * NSPAR + m0 + mm) * NR + rr];
    }
    __syncthreads();
    float acc[8];
#pragma unroll
    for (int mm = 0; mm < 8; mm++) acc[mm] = 0.0f;
    for (int r = 0; r < NR; ++r) {
        float cv = Cp[(size_t)(g * NR + r) * DIN + col];
#pragma unroll
        for (int mm = 0; mm < 8; mm++) acc[mm] += Bs[mm][r] * cv;
    }
#pragma unroll
    for (int mm = 0; mm < 8; mm++)
        Wp[(size_t)(g * DH + NR + m0 + mm) * DIN + col] = acc[mm];
}

// pack Wh -> fp16 k-pair-interleaved: g_Whs[ntile][k>>1][n*2 + (k&1)]
__global__ void k_pack() {
    int i = blockIdx.x * blockDim.x + threadIdx.x;     // 64*1024*64
    if (i >= 64 * DH * 64) return;
    int n     = i & 63;
    int k     = (i >> 6) & (DH - 1);
    int ntile = i >> 16;
    int ng = (n >> 4) * DH + ntile * 16 + (n & 15);
    size_t dst = ((size_t)ntile * 512 + (k >> 1)) * 128 + n * 2 + (k & 1);
    g_Whs[dst] = __float2half_rn(g_Wh[(size_t)ng * DH + k]);
}

// ---------------- X GEMM: preX = x @ Wx^T + bias (tf32 mma.sync, unchanged) ----------------
__global__ __launch_bounds__(256) void k_xgemm(const float* __restrict__ x) {
    __shared__ float As[128][36];
    __shared__ float Bs[128][36];
    const int tid  = threadIdx.x;
    const int lane = tid & 31;
    const int warp = tid >> 5;
    const int wm   = warp & 1;
    const int wn   = warp >> 1;
    const size_t mBase = (size_t)blockIdx.y * 128;
    const int    nBase = blockIdx.x * 128;
    const int lr = tid >> 3;
    const int lc = (tid & 7) * 4;

    float acc[4][4][4];
#pragma unroll
    for (int a = 0; a < 4; a++)
#pragma unroll
        for (int b = 0; b < 4; b++)
#pragma unroll
            for (int d = 0; d < 4; d++) acc[a][b][d] = 0.0f;

    float4 ra[4], rb[4];
#pragma unroll
    for (int p = 0; p < 4; p++) {
        int r = lr + p * 32;
        ra[p] = *(const float4*)&x[(mBase + r) * DIN + lc];
        rb[p] = *(const float4*)&g_Wx[((size_t)(nBase + r)) * DIN + lc];
    }
    for (int k0 = 0; k0 < DIN; k0 += 32) {
#pragma unroll
        for (int p = 0; p < 4; p++) {
            int r = lr + p * 32;
            *(float4*)&As[r][lc] = ra[p];
            *(float4*)&Bs[r][lc] = rb[p];
        }
        __syncthreads();
        int kn = k0 + 32;
        if (kn < DIN) {
#pragma unroll
            for (int p = 0; p < 4; p++) {
                int r = lr + p * 32;
                ra[p] = *(const float4*)&x[(mBase + r) * DIN + kn + lc];
                rb[p] = *(const float4*)&g_Wx[((size_t)(nBase + r)) * DIN + kn + lc];
            }
        }
#pragma unroll
        for (int kk = 0; kk < 32; kk += 8) {
            uint32_t af[4][4];
            uint32_t bf[4][2];
#pragma unroll
            for (int mf = 0; mf < 4; mf++) {
                int rb0 = wm * 64 + mf * 16 + (lane >> 2);
                af[mf][0] = f2tf32(As[rb0][kk + (lane & 3)]);
                af[mf][1] = f2tf32(As[rb0 + 8][kk + (lane & 3)]);
                af[mf][2] = f2tf32(As[rb0][kk + 4 + (lane & 3)]);
                af[mf][3] = f2tf32(As[rb0 + 8][kk + 4 + (lane & 3)]);
            }
#pragma unroll
            for (int nf = 0; nf < 4; nf++) {
                int nb0 = wn * 32 + nf * 8 + (lane >> 2);
                bf[nf][0] = f2tf32(Bs[nb0][kk + (lane & 3)]);
                bf[nf][1] = f2tf32(Bs[nb0][kk + 4 + (lane & 3)]);
            }
#pragma unroll
            for (int mf = 0; mf < 4; mf++)
#pragma unroll
                for (int nf = 0; nf < 4; nf++)
                    mma_tf32(acc[mf][nf], af[mf], bf[nf]);
        }
        __syncthreads();
    }
#pragma unroll
    for (int mf = 0; mf < 4; mf++) {
#pragma unroll
        for (int nf = 0; nf < 4; nf++) {
            int r0 = wm * 64 + mf * 16 + (lane >> 2);
            int c0 = wn * 32 + nf * 8 + (lane & 3) * 2;
            int n  = nBase + c0;
            size_t base = (mBase + r0) * (size_t)N4 + n;
            g_preX[base]                      = acc[mf][nf][0] + g_bias[n];
            g_preX[base + 1]                  = acc[mf][nf][1] + g_bias[n + 1];
            g_preX[base + 8 * (size_t)N4]     = acc[mf][nf][2] + g_bias[n];
            g_preX[base + 8 * (size_t)N4 + 1] = acc[mf][nf][3] + g_bias[n + 1];
        }
    }
}

// ---------------- persistent M-split fp16 recurrence ----------------
// 128 CTAs x 256 thr. CTA = bhalf*64 + ntile: M=64 rows, N=64 gate-cols, K=1024 in fp16.
// 8 warps: 4 tile positions (32m x 32n) x 2 K-interleave groups; merge via smem; own epilogue.
__global__ __launch_bounds__(256) void k_rnn(const float* __restrict__ c0,
                                             float* __restrict__ out) {
    extern __shared__ char dsm[];
    const int tid   = threadIdx.x;
    const int lane  = tid & 31;
    const int warp  = tid >> 5;
    const int cta   = blockIdx.x;
    const int ntile = cta & 63;
    const int bhalf = cta >> 6;
    const int bh64  = bhalf * 64;
    const int wq    = warp & 3;
    const int kpar  = warp >> 2;
    const int wm    = wq & 1;          // m offset 0/32
    const int wn    = wq >> 1;         // n offset 0/32
    const int q     = lane & 3;
    float* Ps = (float*)dsm;           // [64][68] overlay after compute

    const uint32_t dynb = smem_u32(dsm);

    const int er = tid & 63;
    const int ug = tid >> 6;
    const int eb = bh64 + er;

    float cst[4];
    {
        float4 cv = *(const float4*)&c0[(size_t)eb * DH + ntile * 16 + ug * 4];
        cst[0] = cv.x; cst[1] = cv.y; cst[2] = cv.z; cst[3] = cv.w;
    }

    for (int t = 0; t < TSTEPS; ++t) {
        const int src = t & 1;
        const __half* __restrict__ hsrc = g_h[src];

        auto issue = [&](int cc) {
            uint32_t sb = dynb + (cc % 3) * STG_BYTES;
#pragma unroll
            for (int i = 0; i < 8; i++) {
                int s = tid + i * 256;              // 0..2047
                if (s < 1024) {
                    int r = s >> 4, seg = s & 15;
                    cp16(sb + (uint32_t)(r * HSTRB + seg * 16),
                         &hsrc[(size_t)(bh64 + r) * DH + cc * KCH + seg * 8]);
                } else {
                    int v = s - 1024;               // 0..1023
                    int kl = v >> 4, seg = v & 15;
                    cp16(sb + (uint32_t)(64 * HSTRB + kl * WSTRB + seg * 16),
                         &g_Whs[((size_t)ntile * 512 + cc * 64 + kl) * 128 + seg * 8]);
                }
            }
            asm volatile("cp.async.commit_group;" ::: "memory");
        };

        issue(0); issue(1); issue(2);

        // prefetch preX for this thread's epilogue slice
        float4 px[4];
        {
            size_t pxb = ((size_t)t * NB + eb) * N4 + ntile * 16 + ug * 4;
#pragma unroll
            for (int g = 0; g < 4; g++)
                px[g] = *(const float4*)&g_preX[pxb + (size_t)g * DH];
        }

        float acc[2][4][4];
#pragma unroll
        for (int a = 0; a < 2; a++)
#pragma unroll
            for (int c = 0; c < 4; c++)
#pragma unroll
                for (int d = 0; d < 4; d++) acc[a][c][d] = 0.0f;

        for (int ch = 0; ch < NCH; ++ch) {
            if (ch < NCH - 2)       asm volatile("cp.async.wait_group 2;" ::: "memory");
            else if (ch == NCH - 2) asm volatile("cp.async.wait_group 1;" ::: "memory");
            else                    asm volatile("cp.async.wait_group 0;" ::: "memory");
            __syncthreads();

            const char* HsB = dsm + (ch % 3) * STG_BYTES;
            const char* WsB = HsB + 64 * HSTRB;
#pragma unroll
            for (int k16 = 0; k16 < 8; k16 += 2) {
                const int kb = (k16 + kpar) * 16;       // k base within chunk
                uint32_t af[2][4];
#pragma unroll
                for (int mf = 0; mf < 2; mf++) {
                    int r0 = wm * 32 + mf * 16 + (lane >> 2);
                    af[mf][0] = *(const uint32_t*)(HsB + r0 * HSTRB + (kb + 2 * q) * 2);
                    af[mf][1] = *(const uint32_t*)(HsB + (r0 + 8) * HSTRB + (kb + 2 * q) * 2);
                    af[mf][2] = *(const uint32_t*)(HsB + r0 * HSTRB + (kb + 8 + 2 * q) * 2);
                    af[mf][3] = *(const uint32_t*)(HsB + (r0 + 8) * HSTRB + (kb + 8 + 2 * q) * 2);
                }
#pragma unroll
                for (int nf = 0; nf < 4; nf++) {
                    uint32_t bf[2];
                    int n0 = wn * 32 + nf * 8 + (lane >> 2);
                    bf[0] = *(const uint32_t*)(WsB + (kb / 2 + q) * WSTRB + n0 * 4);
                    bf[1] = *(const uint32_t*)(WsB + (kb / 2 + 4 + q) * WSTRB + n0 * 4);
#pragma unroll
                    for (int mf = 0; mf < 2; mf++)
                        mma_f16(acc[mf][nf], af[mf], bf);
                }
            }
            __syncthreads();
            if (ch + 3 < NCH) issue(ch + 3);
        }

        // merge K-interleave halves through Ps, then epilogue
        if (kpar == 1) {
#pragma unroll
            for (int mf = 0; mf < 2; mf++) {
#pragma unroll
                for (int nf = 0; nf < 4; nf++) {
                    int r0 = wm * 32 + mf * 16 + (lane >> 2);
                    int c0i = wn * 32 + nf * 8 + q * 2;
                    Ps[r0 * 68 + c0i]           = acc[mf][nf][0];
                    Ps[r0 * 68 + c0i + 1]       = acc[mf][nf][1];
                    Ps[(r0 + 8) * 68 + c0i]     = acc[mf][nf][2];
                    Ps[(r0 + 8) * 68 + c0i + 1] = acc[mf][nf][3];
                }
            }
        }
        __syncthreads();
        if (kpar == 0) {
#pragma unroll
            for (int mf = 0; mf < 2; mf++) {
#pragma unroll
                for (int nf = 0; nf < 4; nf++) {
                    int r0 = wm * 32 + mf * 16 + (lane >> 2);
                    int c0i = wn * 32 + nf * 8 + q * 2;
                    Ps[r0 * 68 + c0i]           += acc[mf][nf][0];
                    Ps[r0 * 68 + c0i + 1]       += acc[mf][nf][1];
                    Ps[(r0 + 8) * 68 + c0i]     += acc[mf][nf][2];
                    Ps[(r0 + 8) * 68 + c0i + 1] += acc[mf][nf][3];
                }
            }
        }
        __syncthreads();

        // pointwise LSTM: thread -> (row er, units ug*4..+3)
        {
            __half* __restrict__ hdst = g_h[src ^ 1];
            float hv[4];
#pragma unroll
            for (int i = 0; i < 4; i++) {
                int jc = ug * 4 + i;
                float f  = fsigmoid(Ps[er * 68 + jc]      + ((const float*)&px[0])[i]);
                float ii = fsigmoid(Ps[er * 68 + 16 + jc] + ((const float*)&px[1])[i]);
                float gg = tanhf(Ps[er * 68 + 32 + jc]    + ((const float*)&px[2])[i]);
                float oo = fsigmoid(Ps[er * 68 + 48 + jc] + ((const float*)&px[3])[i]);
                float nc = f * cst[i] + ii * gg;
                cst[i] = nc;
                hv[i] = oo * tanhf(nc);
            }
            size_t oo = ((size_t)t * NB + eb) * DH + ntile * 16 + ug * 4;
            *(float4*)&out[oo] = make_float4(hv[0], hv[1], hv[2], hv[3]);
            __half2 h2a = __floats2half2_rn(hv[0], hv[1]);
            __half2 h2b = __floats2half2_rn(hv[2], hv[3]);
            size_t hb = (size_t)eb * DH + ntile * 16 + ug * 4;
            *(__half2*)&hdst[hb]     = h2a;
            *(__half2*)&hdst[hb + 2] = h2b;
            if (t == TSTEPS - 1) {
                size_t fb = (size_t)TSTEPS * NB * DH + (size_t)eb * DH + ntile * 16 + ug * 4;
                *(float4*)&out[fb] = make_float4(hv[0], hv[1], hv[2], hv[3]);
                *(float4*)&out[fb + (size_t)NB * DH] = make_float4(cst[0], cst[1], cst[2], cst[3]);
            }
        }

        // two-level tree barrier
        __threadfence();
        __syncthreads();
        if (tid == 0) {
            unsigned r = atomicAdd(&g_barg[cta >> 4], 1u);
            if (r == 16u * (unsigned)(t + 1) - 1u) {
                __threadfence();
                atomicAdd(&g_root, 1u);
            }
            while (ld_acq(&g_root) < 8u * (unsigned)(t + 1)) { }
        }
        __syncthreads();
    }
}

// ---------------- launch ----------------
extern "C" void kernel_launch(void* const* d_in, const int* in_sizes, int n_in,
                              void* d_out, int out_size) {
    const float* x  = (const float*)d_in[0];
    const float* h0 = (const float*)d_in[1];
    const float* c0 = (const float*)d_in[2];
    const float* Ax = (const float*)d_in[3];
    const float* Bx = (const float*)d_in[4];
    const float* Cx = (const float*)d_in[5];
    const float* Ah = (const float*)d_in[6];
    const float* Bh = (const float*)d_in[7];
    const float* Ch = (const float*)d_in[8];
    const float* bx = (const float*)d_in[9];
    const float* bh = (const float*)d_in[10];
    float* out = (float*)d_out;

    const int smem_bytes = 3 * STG_BYTES;     // 107520
    cudaFuncSetAttribute(k_rnn, cudaFuncAttributeMaxDynamicSharedMemorySize, smem_bytes);

    k_init<<<(NB * DH + 255) / 256, 256>>>(h0);
    k_rich_bias<<<(4 * NR * DIN + 255) / 256, 256>>>(Ax, Ah, bx, bh);
    dim3 gs(DIN / 128, NSPAR / 8, 8);
    k_spar<<<gs, 128>>>(Bx, Cx, Bh, Ch);
    k_pack<<<(64 * DH * 64 + 255) / 256, 256>>>();
    dim3 gx(N4 / 128, (TSTEPS * NB) / 128);
    k_xgemm<<<gx, 256>>>(x);
    k_rnn<<<RCTAS, 256, smem_bytes>>>(c0, out);
}

// round 10
// speedup vs baseline: 4.5667x; 1.2577x over previous
#include <cuda_runtime.h>
#include <cuda_fp16.h>
#include <cstdint>
#include <cstddef>

#define TSTEPS 512
#define NB     128
#define DIN    1024
#define DH     1024
#define NR     256
#define N4     4096
#define NSPAR  768
#define RCTAS  128        // 2 batch-halves x 64 N-tiles
#define KCH    128
#define NCH    8          // DH/KCH
#define HSTRB  272        // rnn Hs row stride bytes
#define WSTRB  288        // rnn Ws k-pair row stride bytes
#define STG_BYTES (64 * HSTRB + 64 * WSTRB)    // 35840
// xgemm fp16 staging
#define XASTR  144        // A row stride bytes (128 data + 16 pad)
#define XBSTR  544        // B k-pair row stride bytes (512 data + 32 pad)
#define XSTG_BYTES (128 * XASTR + 32 * XBSTR)  // 18432 + 17408 = 35840

// ---- static device scratch ----
__device__ float g_Wx[(size_t)N4 * DIN];
__device__ float g_Wh[(size_t)N4 * DH];
__device__ float g_bias[N4];
__device__ float g_preX[(size_t)TSTEPS * NB * N4];          // 1 GiB
__device__ __half g_xh[(size_t)TSTEPS * NB * DIN];          // x in fp16 (134 MB)
__device__ __half g_Wxh[(size_t)32 * 512 * 256];            // [nblk][kpair][n*2+par] fp16
__device__ __half g_Whs[(size_t)64 * 512 * 128];            // [ntile][kpair][n*2+par] fp16
__device__ __half g_h[2][NB * DH];                          // h ping-pong (fp16)
__device__ unsigned g_barg[8];
__device__ unsigned g_root;

// ================= helpers =================
__device__ __forceinline__ void mma_f16(float* c, const uint32_t* a, const uint32_t* b) {
    asm volatile("mma.sync.aligned.m16n8k16.row.col.f32.f16.f16.f32 "
                 "{%0,%1,%2,%3}, {%4,%5,%6,%7}, {%8,%9}, {%0,%1,%2,%3};"
                 : "+f"(c[0]), "+f"(c[1]), "+f"(c[2]), "+f"(c[3])
                 : "r"(a[0]), "r"(a[1]), "r"(a[2]), "r"(a[3]), "r"(b[0]), "r"(b[1]));
}
__device__ __forceinline__ float fsigmoid(float x) { return 1.0f / (1.0f + __expf(-x)); }

__device__ __forceinline__ uint32_t smem_u32(const void* p) {
    uint32_t a;
    asm("{ .reg .u64 t; cvta.to.shared.u64 t, %1; cvt.u32.u64 %0, t; }" : "=r"(a) : "l"(p));
    return a;
}
__device__ __forceinline__ void cp16(uint32_t dst, const void* src) {
    asm volatile("cp.async.cg.shared.global [%0], [%1], 16;" :: "r"(dst), "l"(src));
}
__device__ __forceinline__ unsigned ld_acq(const unsigned* p) {
    unsigned v;
    asm volatile("ld.acquire.gpu.global.u32 %0, [%1];" : "=r"(v) : "l"(p) : "memory");
    return v;
}

// ================= prep kernels =================
__global__ void k_init(const float* __restrict__ h0) {
    int i = blockIdx.x * blockDim.x + threadIdx.x;
    if (i < NB * DH) g_h[0][i] = __float2half_rn(h0[i]);
    if (i < 8) g_barg[i] = 0;
    if (i == 0) g_root = 0;
}

__global__ void k_rich_bias(const float* __restrict__ Ax, const float* __restrict__ Ah,
                            const float* __restrict__ bx, const float* __restrict__ bh) {
    int i = blockIdx.x * blockDim.x + threadIdx.x;
    if (i < 4 * NR * DIN) {
        int k = i % DIN, row = i / DIN;
        int g = row / NR, j = row % NR;
        size_t w = ((size_t)(g * DH + j)) * DIN + k;
        g_Wx[w] = Ax[i];
        g_Wh[w] = Ah[i];
    }
    if (i < N4) g_bias[i] = bx[i] + bh[i];
}

__global__ void k_spar(const float* __restrict__ Bx, const float* __restrict__ Cx,
                       const float* __restrict__ Bh, const float* __restrict__ Ch) {
    int z = blockIdx.z;
    int g = z & 3;
    const float* Bp = (z < 4) ? Bx : Bh;
    const float* Cp = (z < 4) ? Cx : Ch;
    float*       Wp = (z < 4) ? g_Wx : g_Wh;
    int m0  = blockIdx.y * 8;
    int col = blockIdx.x * 128 + threadIdx.x;

    __shared__ float Bs[8][NR];
    for (int i = threadIdx.x; i < 8 * NR; i += 128) {
        int mm = i / NR, rr = i % NR;
        Bs[mm][rr] = Bp[(size_t)(g * NSPAR + m0 + mm) * NR + rr];
    }
    __syncthreads();
    float acc[8];
#pragma unroll
    for (int mm = 0; mm < 8; mm++) acc[mm] = 0.0f;
    for (int r = 0; r < NR; ++r) {
        float cv = Cp[(size_t)(g * NR + r) * DIN + col];
#pragma unroll
        for (int mm = 0; mm < 8; mm++) acc[mm] += Bs[mm][r] * cv;
    }
#pragma unroll
    for (int mm = 0; mm < 8; mm++)
        Wp[(size_t)(g * DH + NR + m0 + mm) * DIN + col] = acc[mm];
}

// pack Wh -> fp16 k-pair-interleaved: g_Whs[ntile][k>>1][n*2 + (k&1)]
__global__ void k_pack() {
    int i = blockIdx.x * blockDim.x + threadIdx.x;     // 64*1024*64
    if (i >= 64 * DH * 64) return;
    int n     = i & 63;
    int k     = (i >> 6) & (DH - 1);
    int ntile = i >> 16;
    int ng = (n >> 4) * DH + ntile * 16 + (n & 15);
    size_t dst = ((size_t)ntile * 512 + (k >> 1)) * 128 + n * 2 + (k & 1);
    g_Whs[dst] = __float2half_rn(g_Wh[(size_t)ng * DH + k]);
}

// pack Wx -> fp16 k-pair-interleaved per 128-n block: g_Wxh[nb][k>>1][nl*2 + (k&1)]
__global__ void k_packx() {
    int i = blockIdx.x * blockDim.x + threadIdx.x;     // N4*DIN = 4,194,304
    if (i >= N4 * DIN) return;
    int k = i & (DIN - 1);
    int n = i >> 10;
    int nb = n >> 7, nl = n & 127;
    size_t dst = ((size_t)nb * 512 + (k >> 1)) * 256 + nl * 2 + (k & 1);
    g_Wxh[dst] = __float2half_rn(g_Wx[(size_t)n * DIN + k]);
}

// convert x -> fp16 (vectorized 4/thread)
__global__ void k_cvtx(const float* __restrict__ x) {
    size_t i = ((size_t)blockIdx.x * blockDim.x + threadIdx.x) * 4;
    if (i >= (size_t)TSTEPS * NB * DIN) return;
    float4 v = *(const float4*)&x[i];
    __half2 a = __floats2half2_rn(v.x, v.y);
    __half2 b = __floats2half2_rn(v.z, v.w);
    *(__half2*)&g_xh[i]     = a;
    *(__half2*)&g_xh[i + 2] = b;
}

// ---------------- X GEMM fp16: preX = x @ Wx^T + bias ----------------
// grid (32, 512), 256 thr (8 warps 2m x 4n, warp tile 64x32). BK=64, 16 chunks, 3-stage cp.async.
__global__ __launch_bounds__(256) void k_xgemm16() {
    extern __shared__ char xsm[];
    const int tid  = threadIdx.x;
    const int lane = tid & 31;
    const int warp = tid >> 5;
    const int wm   = warp & 1;
    const int wn   = warp >> 1;
    const int q    = lane & 3;
    const size_t mBase = (size_t)blockIdx.y * 128;
    const int    nb    = blockIdx.x;

    auto issue = [&](int cc) {
        uint32_t sb = smem_u32(xsm) + (cc % 3) * XSTG_BYTES;
#pragma unroll
        for (int i = 0; i < 8; i++) {
            int s = tid + i * 256;               // 0..2047
            if (s < 1024) {
                int r = s >> 3, seg = s & 7;
                cp16(sb + (uint32_t)(r * XASTR + seg * 16),
                     &g_xh[(mBase + r) * DIN + cc * 64 + seg * 8]);
            } else {
                int v = s - 1024;                // 0..1023
                int kl = v >> 5, seg = v & 31;
                cp16(sb + (uint32_t)(128 * XASTR + kl * XBSTR + seg * 16),
                     &g_Wxh[((size_t)nb * 512 + cc * 32 + kl) * 256 + seg * 8]);
            }
        }
        asm volatile("cp.async.commit_group;" ::: "memory");
    };

    issue(0); issue(1); issue(2);

    float acc[4][4][4];
#pragma unroll
    for (int a = 0; a < 4; a++)
#pragma unroll
        for (int b = 0; b < 4; b++)
#pragma unroll
            for (int d = 0; d < 4; d++) acc[a][b][d] = 0.0f;

    for (int ch = 0; ch < 16; ++ch) {
        if (ch < 14)       asm volatile("cp.async.wait_group 2;" ::: "memory");
        else if (ch == 14) asm volatile("cp.async.wait_group 1;" ::: "memory");
        else               asm volatile("cp.async.wait_group 0;" ::: "memory");
        __syncthreads();

        const char* HsB = xsm + (ch % 3) * XSTG_BYTES;
        const char* WsB = HsB + 128 * XASTR;
#pragma unroll
        for (int k16 = 0; k16 < 4; k16++) {
            const int kb = k16 * 16;
            uint32_t af[4][4];
#pragma unroll
            for (int mf = 0; mf < 4; mf++) {
                int r0 = wm * 64 + mf * 16 + (lane >> 2);
                af[mf][0] = *(const uint32_t*)(HsB + r0 * XASTR + (kb + 2 * q) * 2);
                af[mf][1] = *(const uint32_t*)(HsB + (r0 + 8) * XASTR + (kb + 2 * q) * 2);
                af[mf][2] = *(const uint32_t*)(HsB + r0 * XASTR + (kb + 8 + 2 * q) * 2);
                af[mf][3] = *(const uint32_t*)(HsB + (r0 + 8) * XASTR + (kb + 8 + 2 * q) * 2);
            }
#pragma unroll
            for (int nf = 0; nf < 4; nf++) {
                uint32_t bf[2];
                int n0 = wn * 32 + nf * 8 + (lane >> 2);
                bf[0] = *(const uint32_t*)(WsB + (kb / 2 + q) * XBSTR + n0 * 4);
                bf[1] = *(const uint32_t*)(WsB + (kb / 2 + 4 + q) * XBSTR + n0 * 4);
#pragma unroll
                for (int mf = 0; mf < 4; mf++)
                    mma_f16(acc[mf][nf], af[mf], bf);
            }
        }
        __syncthreads();
        if (ch + 3 < 16) issue(ch + 3);
    }

    const int nBase = nb * 128;
#pragma unroll
    for (int mf = 0; mf < 4; mf++) {
#pragma unroll
        for (int nf = 0; nf < 4; nf++) {
            int r0 = wm * 64 + mf * 16 + (lane >> 2);
            int c0 = wn * 32 + nf * 8 + (lane & 3) * 2;
            int n  = nBase + c0;
            size_t base = (mBase + r0) * (size_t)N4 + n;
            g_preX[base]                      = acc[mf][nf][0] + g_bias[n];
            g_preX[base + 1]                  = acc[mf][nf][1] + g_bias[n + 1];
            g_preX[base + 8 * (size_t)N4]     = acc[mf][nf][2] + g_bias[n];
            g_preX[base + 8 * (size_t)N4 + 1] = acc[mf][nf][3] + g_bias[n + 1];
        }
    }
}

// ---------------- persistent M-split fp16 recurrence (unchanged from R9) ----------------
__global__ __launch_bounds__(256) void k_rnn(const float* __restrict__ c0,
                                             float* __restrict__ out) {
    extern __shared__ char dsm[];
    const int tid   = threadIdx.x;
    const int lane  = tid & 31;
    const int warp  = tid >> 5;
    const int cta   = blockIdx.x;
    const int ntile = cta & 63;
    const int bhalf = cta >> 6;
    const int bh64  = bhalf * 64;
    const int wq    = warp & 3;
    const int kpar  = warp >> 2;
    const int wm    = wq & 1;
    const int wn    = wq >> 1;
    const int q     = lane & 3;
    float* Ps = (float*)dsm;

    const uint32_t dynb = smem_u32(dsm);

    const int er = tid & 63;
    const int ug = tid >> 6;
    const int eb = bh64 + er;

    float cst[4];
    {
        float4 cv = *(const float4*)&c0[(size_t)eb * DH + ntile * 16 + ug * 4];
        cst[0] = cv.x; cst[1] = cv.y; cst[2] = cv.z; cst[3] = cv.w;
    }

    for (int t = 0; t < TSTEPS; ++t) {
        const int src = t & 1;
        const __half* __restrict__ hsrc = g_h[src];

        auto issue = [&](int cc) {
            uint32_t sb = dynb + (cc % 3) * STG_BYTES;
#pragma unroll
            for (int i = 0; i < 8; i++) {
                int s = tid + i * 256;
                if (s < 1024) {
                    int r = s >> 4, seg = s & 15;
                    cp16(sb + (uint32_t)(r * HSTRB + seg * 16),
                         &hsrc[(size_t)(bh64 + r) * DH + cc * KCH + seg * 8]);
                } else {
                    int v = s - 1024;
                    int kl = v >> 4, seg = v & 15;
                    cp16(sb + (uint32_t)(64 * HSTRB + kl * WSTRB + seg * 16),
                         &g_Whs[((size_t)ntile * 512 + cc * 64 + kl) * 128 + seg * 8]);
                }
            }
            asm volatile("cp.async.commit_group;" ::: "memory");
        };

        issue(0); issue(1); issue(2);

        float4 px[4];
        {
            size_t pxb = ((size_t)t * NB + eb) * N4 + ntile * 16 + ug * 4;
#pragma unroll
            for (int g = 0; g < 4; g++)
                px[g] = *(const float4*)&g_preX[pxb + (size_t)g * DH];
        }

        float acc[2][4][4];
#pragma unroll
        for (int a = 0; a < 2; a++)
#pragma unroll
            for (int c = 0; c < 4; c++)
#pragma unroll
                for (int d = 0; d < 4; d++) acc[a][c][d] = 0.0f;

        for (int ch = 0; ch < NCH; ++ch) {
            if (ch < NCH - 2)       asm volatile("cp.async.wait_group 2;" ::: "memory");
            else if (ch == NCH - 2) asm volatile("cp.async.wait_group 1;" ::: "memory");
            else                    asm volatile("cp.async.wait_group 0;" ::: "memory");
            __syncthreads();

            const char* HsB = dsm + (ch % 3) * STG_BYTES;
            const char* WsB = HsB + 64 * HSTRB;
#pragma unroll
            for (int k16 = 0; k16 < 8; k16 += 2) {
                const int kb = (k16 + kpar) * 16;
                uint32_t af[2][4];
#pragma unroll
                for (int mf = 0; mf < 2; mf++) {
                    int r0 = wm * 32 + mf * 16 + (lane >> 2);
                    af[mf][0] = *(const uint32_t*)(HsB + r0 * HSTRB + (kb + 2 * q) * 2);
                    af[mf][1] = *(const uint32_t*)(HsB + (r0 + 8) * HSTRB + (kb + 2 * q) * 2);
                    af[mf][2] = *(const uint32_t*)(HsB + r0 * HSTRB + (kb + 8 + 2 * q) * 2);
                    af[mf][3] = *(const uint32_t*)(HsB + (r0 + 8) * HSTRB + (kb + 8 + 2 * q) * 2);
                }
#pragma unroll
                for (int nf = 0; nf < 4; nf++) {
                    uint32_t bf[2];
                    int n0 = wn * 32 + nf * 8 + (lane >> 2);
                    bf[0] = *(const uint32_t*)(WsB + (kb / 2 + q) * WSTRB + n0 * 4);
                    bf[1] = *(const uint32_t*)(WsB + (kb / 2 + 4 + q) * WSTRB + n0 * 4);
#pragma unroll
                    for (int mf = 0; mf < 2; mf++)
                        mma_f16(acc[mf][nf], af[mf], bf);
                }
            }
            __syncthreads();
            if (ch + 3 < NCH) issue(ch + 3);
        }

        if (kpar == 1) {
#pragma unroll
            for (int mf = 0; mf < 2; mf++) {
#pragma unroll
                for (int nf = 0; nf < 4; nf++) {
                    int r0 = wm * 32 + mf * 16 + (lane >> 2);
                    int c0i = wn * 32 + nf * 8 + q * 2;
                    Ps[r0 * 68 + c0i]           = acc[mf][nf][0];
                    Ps[r0 * 68 + c0i + 1]       = acc[mf][nf][1];
                    Ps[(r0 + 8) * 68 + c0i]     = acc[mf][nf][2];
                    Ps[(r0 + 8) * 68 + c0i + 1] = acc[mf][nf][3];
                }
            }
        }
        __syncthreads();
        if (kpar == 0) {
#pragma unroll
            for (int mf = 0; mf < 2; mf++) {
#pragma unroll
                for (int nf = 0; nf < 4; nf++) {
                    int r0 = wm * 32 + mf * 16 + (lane >> 2);
                    int c0i = wn * 32 + nf * 8 + q * 2;
                    Ps[r0 * 68 + c0i]           += acc[mf][nf][0];
                    Ps[r0 * 68 + c0i + 1]       += acc[mf][nf][1];
                    Ps[(r0 + 8) * 68 + c0i]     += acc[mf][nf][2];
                    Ps[(r0 + 8) * 68 + c0i + 1] += acc[mf][nf][3];
                }
            }
        }
        __syncthreads();

        {
            __half* __restrict__ hdst = g_h[src ^ 1];
            float hv[4];
#pragma unroll
            for (int i = 0; i < 4; i++) {
                int jc = ug * 4 + i;
                float f  = fsigmoid(Ps[er * 68 + jc]      + ((const float*)&px[0])[i]);
                float ii = fsigmoid(Ps[er * 68 + 16 + jc] + ((const float*)&px[1])[i]);
                float gg = tanhf(Ps[er * 68 + 32 + jc]    + ((const float*)&px[2])[i]);
                float oo = fsigmoid(Ps[er * 68 + 48 + jc] + ((const float*)&px[3])[i]);
                float nc = f * cst[i] + ii * gg;
                cst[i] = nc;
                hv[i] = oo * tanhf(nc);
            }
            size_t oo = ((size_t)t * NB + eb) * DH + ntile * 16 + ug * 4;
            *(float4*)&out[oo] = make_float4(hv[0], hv[1], hv[2], hv[3]);
            __half2 h2a = __floats2half2_rn(hv[0], hv[1]);
            __half2 h2b = __floats2half2_rn(hv[2], hv[3]);
            size_t hb = (size_t)eb * DH + ntile * 16 + ug * 4;
            *(__half2*)&hdst[hb]     = h2a;
            *(__half2*)&hdst[hb + 2] = h2b;
            if (t == TSTEPS - 1) {
                size_t fb = (size_t)TSTEPS * NB * DH + (size_t)eb * DH + ntile * 16 + ug * 4;
                *(float4*)&out[fb] = make_float4(hv[0], hv[1], hv[2], hv[3]);
                *(float4*)&out[fb + (size_t)NB * DH] = make_float4(cst[0], cst[1], cst[2], cst[3]);
            }
        }

        __threadfence();
        __syncthreads();
        if (tid == 0) {
            unsigned r = atomicAdd(&g_barg[cta >> 4], 1u);
            if (r == 16u * (unsigned)(t + 1) - 1u) {
                __threadfence();
                atomicAdd(&g_root, 1u);
            }
            while (ld_acq(&g_root) < 8u * (unsigned)(t + 1)) { }
        }
        __syncthreads();
    }
}

// ---------------- launch ----------------
extern "C" void kernel_launch(void* const* d_in, const int* in_sizes, int n_in,
                              void* d_out, int out_size) {
    const float* x  = (const float*)d_in[0];
    const float* h0 = (const float*)d_in[1];
    const float* c0 = (const float*)d_in[2];
    const float* Ax = (const float*)d_in[3];
    const float* Bx = (const float*)d_in[4];
    const float* Cx = (const float*)d_in[5];
    const float* Ah = (const float*)d_in[6];
    const float* Bh = (const float*)d_in[7];
    const float* Ch = (const float*)d_in[8];
    const float* bx = (const float*)d_in[9];
    const float* bh = (const float*)d_in[10];
    float* out = (float*)d_out;

    const int rnn_smem = 3 * STG_BYTES;       // 107520
    const int xg_smem  = 3 * XSTG_BYTES;      // 107520
    cudaFuncSetAttribute(k_rnn, cudaFuncAttributeMaxDynamicSharedMemorySize, rnn_smem);
    cudaFuncSetAttribute(k_xgemm16, cudaFuncAttributeMaxDynamicSharedMemorySize, xg_smem);

    k_init<<<(NB * DH + 255) / 256, 256>>>(h0);
    k_rich_bias<<<(4 * NR * DIN + 255) / 256, 256>>>(Ax, Ah, bx, bh);
    dim3 gs(DIN / 128, NSPAR / 8, 8);
    k_spar<<<gs, 128>>>(Bx, Cx, Bh, Ch);
    k_pack<<<(64 * DH * 64 + 255) / 256, 256>>>();
    k_packx<<<(N4 * DIN + 255) / 256, 256>>>();
    k_cvtx<<<(int)(((size_t)TSTEPS * NB * DIN / 4 + 255) / 256), 256>>>(x);
    dim3 gx(N4 / 128, (TSTEPS * NB) / 128);
    k_xgemm16<<<gx, 256, xg_smem>>>();
    k_rnn<<<RCTAS, 256, rnn_smem>>>(c0, out);
}

// round 11
// speedup vs baseline: 4.9297x; 1.0795x over previous
#include <cuda_runtime.h>
#include <cuda_fp16.h>
#include <cstdint>
#include <cstddef>

#define TSTEPS 512
#define NB     128
#define DIN    1024
#define DH     1024
#define NR     256
#define N4     4096
#define NSPAR  768
#define RCTAS  128        // 2 batch-halves x 64 N-tiles
#define KCH    128
#define NCH    8          // DH/KCH
#define HSTRB  272        // h row stride bytes (256 data + 16 pad)
#define WSTRB  288        // W k-pair row stride bytes (256 data + 32 pad)
#define HCHUNK (64 * HSTRB)          // 17408 per h stage
#define WOFF   (3 * HCHUNK)          // 52224
#define WFULL  (512 * WSTRB)         // 147456
#define RNN_SMEM (WOFF + WFULL)      // 199680
// xgemm fp16 staging
#define XASTR  144
#define XBSTR  544
#define XSTG_BYTES (128 * XASTR + 32 * XBSTR)  // 35840

// ---- static device scratch ----
__device__ float g_Wx[(size_t)N4 * DIN];
__device__ float g_Wh[(size_t)N4 * DH];
__device__ float g_bias[N4];
__device__ float g_preX[(size_t)TSTEPS * NB * N4];          // 1 GiB
__device__ __half g_xh[(size_t)TSTEPS * NB * DIN];          // x in fp16
__device__ __half g_Wxh[(size_t)32 * 512 * 256];            // [nblk][kpair][n*2+par]
__device__ __half g_Whs[(size_t)64 * 512 * 128];            // [ntile][kpair][n*2+par]
__device__ __half g_h[2][NB * DH];                          // h ping-pong (fp16)
__device__ unsigned g_barg[8];
__device__ unsigned g_root2[64];                            // per-bhalf root (stride 32)

// ================= helpers =================
__device__ __forceinline__ void mma_f16(float* c, const uint32_t* a, const uint32_t* b) {
    asm volatile("mma.sync.aligned.m16n8k16.row.col.f32.f16.f16.f32 "
                 "{%0,%1,%2,%3}, {%4,%5,%6,%7}, {%8,%9}, {%0,%1,%2,%3};"
                 : "+f"(c[0]), "+f"(c[1]), "+f"(c[2]), "+f"(c[3])
                 : "r"(a[0]), "r"(a[1]), "r"(a[2]), "r"(a[3]), "r"(b[0]), "r"(b[1]));
}
__device__ __forceinline__ float fsigmoid(float x) { return 1.0f / (1.0f + __expf(-x)); }

__device__ __forceinline__ uint32_t smem_u32(const void* p) {
    uint32_t a;
    asm("{ .reg .u64 t; cvta.to.shared.u64 t, %1; cvt.u32.u64 %0, t; }" : "=r"(a) : "l"(p));
    return a;
}
__device__ __forceinline__ void cp16(uint32_t dst, const void* src) {
    asm volatile("cp.async.cg.shared.global [%0], [%1], 16;" :: "r"(dst), "l"(src));
}
__device__ __forceinline__ unsigned ld_acq(const unsigned* p) {
    unsigned v;
    asm volatile("ld.acquire.gpu.global.u32 %0, [%1];" : "=r"(v) : "l"(p) : "memory");
    return v;
}

// ================= prep kernels =================
__global__ void k_init(const float* __restrict__ h0) {
    int i = blockIdx.x * blockDim.x + threadIdx.x;
    if (i < NB * DH) g_h[0][i] = __float2half_rn(h0[i]);
    if (i < 8) g_barg[i] = 0;
    if (i < 64) g_root2[i] = 0;
}

__global__ void k_rich_bias(const float* __restrict__ Ax, const float* __restrict__ Ah,
                            const float* __restrict__ bx, const float* __restrict__ bh) {
    int i = blockIdx.x * blockDim.x + threadIdx.x;
    if (i < 4 * NR * DIN) {
        int k = i % DIN, row = i / DIN;
        int g = row / NR, j = row % NR;
        size_t w = ((size_t)(g * DH + j)) * DIN + k;
        g_Wx[w] = Ax[i];
        g_Wh[w] = Ah[i];
    }
    if (i < N4) g_bias[i] = bx[i] + bh[i];
}

__global__ void k_spar(const float* __restrict__ Bx, const float* __restrict__ Cx,
                       const float* __restrict__ Bh, const float* __restrict__ Ch) {
    int z = blockIdx.z;
    int g = z & 3;
    const float* Bp = (z < 4) ? Bx : Bh;
    const float* Cp = (z < 4) ? Cx : Ch;
    float*       Wp = (z < 4) ? g_Wx : g_Wh;
    int m0  = blockIdx.y * 8;
    int col = blockIdx.x * 128 + threadIdx.x;

    __shared__ float Bs[8][NR];
    for (int i = threadIdx.x; i < 8 * NR; i += 128) {
        int mm = i / NR, rr = i % NR;
        Bs[mm][rr] = Bp[(size_t)(g * NSPAR + m0 + mm) * NR + rr];
    }
    __syncthreads();
    float acc[8];
#pragma unroll
    for (int mm = 0; mm < 8; mm++) acc[mm] = 0.0f;
    for (int r = 0; r < NR; ++r) {
        float cv = Cp[(size_t)(g * NR + r) * DIN + col];
#pragma unroll
        for (int mm = 0; mm < 8; mm++) acc[mm] += Bs[mm][r] * cv;
    }
#pragma unroll
    for (int mm = 0; mm < 8; mm++)
        Wp[(size_t)(g * DH + NR + m0 + mm) * DIN + col] = acc[mm];
}

// pack Wh -> fp16 k-pair-interleaved: g_Whs[ntile][k>>1][n*2 + (k&1)]
__global__ void k_pack() {
    int i = blockIdx.x * blockDim.x + threadIdx.x;
    if (i >= 64 * DH * 64) return;
    int n     = i & 63;
    int k     = (i >> 6) & (DH - 1);
    int ntile = i >> 16;
    int ng = (n >> 4) * DH + ntile * 16 + (n & 15);
    size_t dst = ((size_t)ntile * 512 + (k >> 1)) * 128 + n * 2 + (k & 1);
    g_Whs[dst] = __float2half_rn(g_Wh[(size_t)ng * DH + k]);
}

// pack Wx -> fp16 k-pair-interleaved per 128-n block
__global__ void k_packx() {
    int i = blockIdx.x * blockDim.x + threadIdx.x;
    if (i >= N4 * DIN) return;
    int k = i & (DIN - 1);
    int n = i >> 10;
    int nb = n >> 7, nl = n & 127;
    size_t dst = ((size_t)nb * 512 + (k >> 1)) * 256 + nl * 2 + (k & 1);
    g_Wxh[dst] = __float2half_rn(g_Wx[(size_t)n * DIN + k]);
}

// convert x -> fp16
__global__ void k_cvtx(const float* __restrict__ x) {
    size_t i = ((size_t)blockIdx.x * blockDim.x + threadIdx.x) * 4;
    if (i >= (size_t)TSTEPS * NB * DIN) return;
    float4 v = *(const float4*)&x[i];
    __half2 a = __floats2half2_rn(v.x, v.y);
    __half2 b = __floats2half2_rn(v.z, v.w);
    *(__half2*)&g_xh[i]     = a;
    *(__half2*)&g_xh[i + 2] = b;
}

// ---------------- X GEMM fp16: preX = x @ Wx^T + bias (unchanged from R10) ----------------
__global__ __launch_bounds__(256) void k_xgemm16() {
    extern __shared__ char xsm[];
    const int tid  = threadIdx.x;
    const int lane = tid & 31;
    const int warp = tid >> 5;
    const int wm   = warp & 1;
    const int wn   = warp >> 1;
    const int q    = lane & 3;
    const size_t mBase = (size_t)blockIdx.y * 128;
    const int    nb    = blockIdx.x;

    auto issue = [&](int cc) {
        uint32_t sb = smem_u32(xsm) + (cc % 3) * XSTG_BYTES;
#pragma unroll
        for (int i = 0; i < 8; i++) {
            int s = tid + i * 256;
            if (s < 1024) {
                int r = s >> 3, seg = s & 7;
                cp16(sb + (uint32_t)(r * XASTR + seg * 16),
                     &g_xh[(mBase + r) * DIN + cc * 64 + seg * 8]);
            } else {
                int v = s - 1024;
                int kl = v >> 5, seg = v & 31;
                cp16(sb + (uint32_t)(128 * XASTR + kl * XBSTR + seg * 16),
                     &g_Wxh[((size_t)nb * 512 + cc * 32 + kl) * 256 + seg * 8]);
            }
        }
        asm volatile("cp.async.commit_group;" ::: "memory");
    };

    issue(0); issue(1); issue(2);

    float acc[4][4][4];
#pragma unroll
    for (int a = 0; a < 4; a++)
#pragma unroll
        for (int b = 0; b < 4; b++)
#pragma unroll
            for (int d = 0; d < 4; d++) acc[a][b][d] = 0.0f;

    for (int ch = 0; ch < 16; ++ch) {
        if (ch < 14)       asm volatile("cp.async.wait_group 2;" ::: "memory");
        else if (ch == 14) asm volatile("cp.async.wait_group 1;" ::: "memory");
        else               asm volatile("cp.async.wait_group 0;" ::: "memory");
        __syncthreads();

        const char* HsB = xsm + (ch % 3) * XSTG_BYTES;
        const char* WsB = HsB + 128 * XASTR;
#pragma unroll
        for (int k16 = 0; k16 < 4; k16++) {
            const int kb = k16 * 16;
            uint32_t af[4][4];
#pragma unroll
            for (int mf = 0; mf < 4; mf++) {
                int r0 = wm * 64 + mf * 16 + (lane >> 2);
                af[mf][0] = *(const uint32_t*)(HsB + r0 * XASTR + (kb + 2 * q) * 2);
                af[mf][1] = *(const uint32_t*)(HsB + (r0 + 8) * XASTR + (kb + 2 * q) * 2);
                af[mf][2] = *(const uint32_t*)(HsB + r0 * XASTR + (kb + 8 + 2 * q) * 2);
                af[mf][3] = *(const uint32_t*)(HsB + (r0 + 8) * XASTR + (kb + 8 + 2 * q) * 2);
            }
#pragma unroll
            for (int nf = 0; nf < 4; nf++) {
                uint32_t bf[2];
                int n0 = wn * 32 + nf * 8 + (lane >> 2);
                bf[0] = *(const uint32_t*)(WsB + (kb / 2 + q) * XBSTR + n0 * 4);
                bf[1] = *(const uint32_t*)(WsB + (kb / 2 + 4 + q) * XBSTR + n0 * 4);
#pragma unroll
                for (int mf = 0; mf < 4; mf++)
                    mma_f16(acc[mf][nf], af[mf], bf);
            }
        }
        __syncthreads();
        if (ch + 3 < 16) issue(ch + 3);
    }

    const int nBase = nb * 128;
#pragma unroll
    for (int mf = 0; mf < 4; mf++) {
#pragma unroll
        for (int nf = 0; nf < 4; nf++) {
            int r0 = wm * 64 + mf * 16 + (lane >> 2);
            int c0 = wn * 32 + nf * 8 + (lane & 3) * 2;
            int n  = nBase + c0;
            size_t base = (mBase + r0) * (size_t)N4 + n;
            g_preX[base]                      = acc[mf][nf][0] + g_bias[n];
            g_preX[base + 1]                  = acc[mf][nf][1] + g_bias[n + 1];
            g_preX[base + 8 * (size_t)N4]     = acc[mf][nf][2] + g_bias[n];
            g_preX[base + 8 * (size_t)N4 + 1] = acc[mf][nf][3] + g_bias[n + 1];
        }
    }
}

// ---------------- persistent M-split fp16 recurrence, W resident in SMEM ----------------
// 128 CTAs x 256 thr. CTA = bhalf*64 + ntile: M=64 rows, N=64 gate-cols, K=1024.
// SMEM: [0, 52224) 3 h-stages (+Psa/Psb overlay), [52224, 199680) resident W.
__global__ __launch_bounds__(256) void k_rnn(const float* __restrict__ c0,
                                             float* __restrict__ out) {
    extern __shared__ char dsm[];
    const int tid   = threadIdx.x;
    const int lane  = tid & 31;
    const int warp  = tid >> 5;
    const int cta   = blockIdx.x;
    const int ntile = cta & 63;
    const int bhalf = cta >> 6;
    const int bh64  = bhalf * 64;
    const int wq    = warp & 3;
    const int kpar  = warp >> 2;
    const int wm    = wq & 1;
    const int wn    = wq >> 1;
    const int q     = lane & 3;
    float* Psa = (float*)dsm;                    // [64][68] overlay on h stage 0
    float* Psb = (float*)(dsm + HCHUNK);         // [64][68] overlay on h stage 1

    const uint32_t dynb = smem_u32(dsm);

    const int er = tid & 63;
    const int ug = tid >> 6;
    const int eb = bh64 + er;

    // load resident W (512 kpair rows x 256B data, stride 288)
    for (int i = tid; i < 8192; i += 256) {
        int row = i >> 4, seg = i & 15;
        cp16(dynb + (uint32_t)(WOFF + row * WSTRB + seg * 16),
             &g_Whs[((size_t)ntile * 512 + row) * 128 + seg * 8]);
    }
    asm volatile("cp.async.commit_group;" ::: "memory");

    float cst[4];
    {
        float4 cv = *(const float4*)&c0[(size_t)eb * DH + ntile * 16 + ug * 4];
        cst[0] = cv.x; cst[1] = cv.y; cst[2] = cv.z; cst[3] = cv.w;
    }
    asm volatile("cp.async.wait_group 0;" ::: "memory");
    __syncthreads();

    for (int t = 0; t < TSTEPS; ++t) {
        const int src = t & 1;
        const __half* __restrict__ hsrc = g_h[src];

        auto issue = [&](int cc) {
            uint32_t sb = dynb + (cc % 3) * HCHUNK;
#pragma unroll
            for (int i = 0; i < 4; i++) {
                int s = tid + i * 256;             // 0..1023
                int r = s >> 4, seg = s & 15;
                cp16(sb + (uint32_t)(r * HSTRB + seg * 16),
                     &hsrc[(size_t)(bh64 + r) * DH + cc * KCH + seg * 8]);
            }
            asm volatile("cp.async.commit_group;" ::: "memory");
        };

        issue(0); issue(1); issue(2);

        float4 px[4];
        {
            size_t pxb = ((size_t)t * NB + eb) * N4 + ntile * 16 + ug * 4;
#pragma unroll
            for (int g = 0; g < 4; g++)
                px[g] = *(const float4*)&g_preX[pxb + (size_t)g * DH];
        }

        float acc[2][4][4];
#pragma unroll
        for (int a = 0; a < 2; a++)
#pragma unroll
            for (int c = 0; c < 4; c++)
#pragma unroll
                for (int d = 0; d < 4; d++) acc[a][c][d] = 0.0f;

        for (int ch = 0; ch < NCH; ++ch) {
            if (ch < NCH - 2)       asm volatile("cp.async.wait_group 2;" ::: "memory");
            else if (ch == NCH - 2) asm volatile("cp.async.wait_group 1;" ::: "memory");
            else                    asm volatile("cp.async.wait_group 0;" ::: "memory");
            __syncthreads();

            const char* HsB = dsm + (ch % 3) * HCHUNK;
            const char* WsB = dsm + WOFF + ch * 64 * WSTRB;
#pragma unroll
            for (int k16 = 0; k16 < 8; k16 += 2) {
                const int kb = (k16 + kpar) * 16;
                uint32_t af[2][4];
#pragma unroll
                for (int mf = 0; mf < 2; mf++) {
                    int r0 = wm * 32 + mf * 16 + (lane >> 2);
                    af[mf][0] = *(const uint32_t*)(HsB + r0 * HSTRB + (kb + 2 * q) * 2);
                    af[mf][1] = *(const uint32_t*)(HsB + (r0 + 8) * HSTRB + (kb + 2 * q) * 2);
                    af[mf][2] = *(const uint32_t*)(HsB + r0 * HSTRB + (kb + 8 + 2 * q) * 2);
                    af[mf][3] = *(const uint32_t*)(HsB + (r0 + 8) * HSTRB + (kb + 8 + 2 * q) * 2);
                }
#pragma unroll
                for (int nf = 0; nf < 4; nf++) {
                    uint32_t bf[2];
                    int n0 = wn * 32 + nf * 8 + (lane >> 2);
                    bf[0] = *(const uint32_t*)(WsB + (kb / 2 + q) * WSTRB + n0 * 4);
                    bf[1] = *(const uint32_t*)(WsB + (kb / 2 + 4 + q) * WSTRB + n0 * 4);
#pragma unroll
                    for (int mf = 0; mf < 2; mf++)
                        mma_f16(acc[mf][nf], af[mf], bf);
                }
            }
            __syncthreads();
            if (ch + 3 < NCH) issue(ch + 3);
        }

        // single-sync merge: both kpar groups store to disjoint Ps arrays
        {
            float* Pd = (kpar == 0) ? Psa : Psb;
#pragma unroll
            for (int mf = 0; mf < 2; mf++) {
#pragma unroll
                for (int nf = 0; nf < 4; nf++) {
                    int r0 = wm * 32 + mf * 16 + (lane >> 2);
                    int c0i = wn * 32 + nf * 8 + q * 2;
                    Pd[r0 * 68 + c0i]           = acc[mf][nf][0];
                    Pd[r0 * 68 + c0i + 1]       = acc[mf][nf][1];
                    Pd[(r0 + 8) * 68 + c0i]     = acc[mf][nf][2];
                    Pd[(r0 + 8) * 68 + c0i + 1] = acc[mf][nf][3];
                }
            }
        }
        __syncthreads();

        // pointwise LSTM: thread -> (row er, units ug*4..+3)
        {
            __half* __restrict__ hdst = g_h[src ^ 1];
            float hv[4];
#pragma unroll
            for (int i = 0; i < 4; i++) {
                int jc = ug * 4 + i;
                float pf = Psa[er * 68 + jc]      + Psb[er * 68 + jc];
                float pi = Psa[er * 68 + 16 + jc] + Psb[er * 68 + 16 + jc];
                float pg = Psa[er * 68 + 32 + jc] + Psb[er * 68 + 32 + jc];
                float po = Psa[er * 68 + 48 + jc] + Psb[er * 68 + 48 + jc];
                float f  = fsigmoid(pf + ((const float*)&px[0])[i]);
                float ii = fsigmoid(pi + ((const float*)&px[1])[i]);
                float gg = tanhf(pg + ((const float*)&px[2])[i]);
                float oo = fsigmoid(po + ((const float*)&px[3])[i]);
                float nc = f * cst[i] + ii * gg;
                cst[i] = nc;
                hv[i] = oo * tanhf(nc);
            }
            size_t oo = ((size_t)t * NB + eb) * DH + ntile * 16 + ug * 4;
            *(float4*)&out[oo] = make_float4(hv[0], hv[1], hv[2], hv[3]);
            __half2 h2a = __floats2half2_rn(hv[0], hv[1]);
            __half2 h2b = __floats2half2_rn(hv[2], hv[3]);
            size_t hb = (size_t)eb * DH + ntile * 16 + ug * 4;
            *(__half2*)&hdst[hb]     = h2a;
            *(__half2*)&hdst[hb + 2] = h2b;
            if (t == TSTEPS - 1) {
                size_t fb = (size_t)TSTEPS * NB * DH + (size_t)eb * DH + ntile * 16 + ug * 4;
                *(float4*)&out[fb] = make_float4(hv[0], hv[1], hv[2], hv[3]);
                *(float4*)&out[fb + (size_t)NB * DH] = make_float4(cst[0], cst[1], cst[2], cst[3]);
            }
        }

        // per-bhalf two-level barrier (groups of 16 CTAs; roots decoupled per bhalf)
        __threadfence();
        __syncthreads();
        if (tid == 0) {
            unsigned r = atomicAdd(&g_barg[cta >> 4], 1u);
            if (r == 16u * (unsigned)(t + 1) - 1u) {
                __threadfence();
                atomicAdd(&g_root2[bhalf * 32], 1u);
            }
            while (ld_acq(&g_root2[bhalf * 32]) < 4u * (unsigned)(t + 1)) { }
        }
        __syncthreads();
    }
}

// ---------------- launch ----------------
extern "C" void kernel_launch(void* const* d_in, const int* in_sizes, int n_in,
                              void* d_out, int out_size) {
    const float* x  = (const float*)d_in[0];
    const float* h0 = (const float*)d_in[1];
    const float* c0 = (const float*)d_in[2];
    const float* Ax = (const float*)d_in[3];
    const float* Bx = (const float*)d_in[4];
    const float* Cx = (const float*)d_in[5];
    const float* Ah = (const float*)d_in[6];
    const float* Bh = (const float*)d_in[7];
    const float* Ch = (const float*)d_in[8];
    const float* bx = (const float*)d_in[9];
    const float* bh = (const float*)d_in[10];
    float* out = (float*)d_out;

    const int xg_smem = 3 * XSTG_BYTES;      // 107520
    cudaFuncSetAttribute(k_rnn, cudaFuncAttributeMaxDynamicSharedMemorySize, RNN_SMEM);
    cudaFuncSetAttribute(k_xgemm16, cudaFuncAttributeMaxDynamicSharedMemorySize, xg_smem);

    k_init<<<(NB * DH + 255) / 256, 256>>>(h0);
    k_rich_bias<<<(4 * NR * DIN + 255) / 256, 256>>>(Ax, Ah, bx, bh);
    dim3 gs(DIN / 128, NSPAR / 8, 8);
    k_spar<<<gs, 128>>>(Bx, Cx, Bh, Ch);
    k_pack<<<(64 * DH * 64 + 255) / 256, 256>>>();
    k_packx<<<(N4 * DIN + 255) / 256, 256>>>();
    k_cvtx<<<(int)(((size_t)TSTEPS * NB * DIN / 4 + 255) / 256), 256>>>(x);
    dim3 gx(N4 / 128, (TSTEPS * NB) / 128);
    k_xgemm16<<<gx, 256, xg_smem>>>();
    k_rnn<<<RCTAS, 256, RNN_SMEM>>>(c0, out);
}